// round 9
// baseline (speedup 1.0000x reference)
#include <cuda_runtime.h>
#include <cuda_bf16.h>
#include <cstdint>

// ---------------------------------------------------------------------------
// Problem constants
// ---------------------------------------------------------------------------
#define NN      20000
#define TT      64
#define FF      128
#define BB      8192
#define KK      32
#define QQ      (3*BB)            // 24576
#define WWIN    64
#define QK      (QQ*KK)           // 786432
#define NTILE   8                 // tiles per persistent block
#define EB      768               // blocks per direction (768*8 = 6144 tiles)

// Edge-kernel dynamic smem layout (bytes)
#define EOFF_A   0                      // As: [128 k][132] f32 (128 e + pad) = 67584
#define EOFF_B   67584                  // Bdup: [128 k][128] f32 (64 j duplicated pairs) = 65536
#define EOFF_D   (EOFF_B + 65536)       // demb: 65x64 f32 = 16640
#define EOFF_P   (EOFF_D + 16640)       // spart: [16][64] f32 = 4096
#define EOFF_M   (EOFF_P + 4096)        // smask[128], sdelta[128], srow[128] int = 1536
#define SMEM_EK  (EOFF_M + 1536)        // 155392 B

// ---------------------------------------------------------------------------
// Device scratch (static __device__ arrays — allocation APIs are forbidden)
// ---------------------------------------------------------------------------
__device__ int    g_mask_mode;                // 0=u8, 1=i32, 2=f32
__device__ float  g_demb[2*65*64];            // per-dir (delta_emb@w1_delta + b1)
__device__ float  g_hsum[2*(size_t)QQ*64];    // per-(dir,query) sum of relu hidden
__device__ int    g_cnt[2*QQ];                // per-(dir,query) valid-edge count
__device__ float  g_feat[(size_t)QQ*256];     // [x_vt | m_in | m_out]
__device__ float  g_u1[(size_t)QQ*128];       // combine hidden 1
__device__ float  g_feat2[(size_t)BB*193];    // scorer features

// ---------------------------------------------------------------------------
// f32x2 helpers (sm_103a packed fp32 — 2x FFMA throughput)
// ---------------------------------------------------------------------------
__device__ __forceinline__ unsigned long long ffma2(unsigned long long a,
                                                    unsigned long long b,
                                                    unsigned long long c) {
    unsigned long long d;
    asm("fma.rn.f32x2 %0, %1, %2, %3;" : "=l"(d) : "l"(a), "l"(b), "l"(c));
    return d;
}
__device__ __forceinline__ unsigned long long dup2(float v) {
    unsigned long long r;
    asm("mov.b64 %0, {%1, %2};" : "=l"(r) : "f"(v), "f"(v));
    return r;
}
__device__ __forceinline__ float2 unpack2(unsigned long long v) {
    float2 r;
    asm("mov.b64 {%0, %1}, %2;" : "=f"(r.x), "=f"(r.y) : "l"(v));
    return r;
}
__device__ __forceinline__ int read_mask(const void* p, int idx, int mode) {
    if (mode == 1) return ((const int*)p)[idx] != 0;
    if (mode == 2) return ((const float*)p)[idx] != 0.0f;
    return ((const unsigned char*)p)[idx] != 0;
}

// ---------------------------------------------------------------------------
// K0: classify mask serialization (u8 / i32 / f32)
// ---------------------------------------------------------------------------
__global__ void its_detect_kernel(const unsigned int* __restrict__ m) {
    __shared__ int not01, not0f;
    if (threadIdx.x == 0) { not01 = 0; not0f = 0; }
    __syncthreads();
    int l01 = 0, l0f = 0;
    for (int i = threadIdx.x; i < QK/4; i += blockDim.x) {
        unsigned v = m[i];
        if (v > 1u) l01 = 1;
        if (v != 0u && v != 0x3F800000u) l0f = 1;
    }
    if (l01) not01 = 1;
    if (l0f) not0f = 1;
    __syncthreads();
    if (threadIdx.x == 0)
        g_mask_mode = (!not01) ? 1 : ((!not0f) ? 2 : 0);
}

// ---------------------------------------------------------------------------
// K1: delta tables: g_demb[dir][d][j] = delta_emb[d] @ w1[128:144, :] + b1[j]
// ---------------------------------------------------------------------------
__global__ void its_tables_kernel(const float* __restrict__ demb,
                                  const float* __restrict__ piw1, const float* __restrict__ pib1,
                                  const float* __restrict__ pow1, const float* __restrict__ pob1) {
    int dir = blockIdx.x;
    const float* w1 = dir ? pow1 : piw1;
    const float* b1 = dir ? pob1 : pib1;
    float* out = g_demb + dir * (65*64);
    for (int idx = threadIdx.x; idx < 65*64; idx += blockDim.x) {
        int d = idx >> 6, j = idx & 63;
        float acc = b1[j];
#pragma unroll
        for (int dd = 0; dd < 16; dd++)
            acc += demb[d*16 + dd] * w1[(128 + dd)*64 + j];
        out[idx] = acc;
    }
}

// ---------------------------------------------------------------------------
// K2: edge aggregation, persistent FFMA2 version.
// Block = 1 dir, NTILE tiles of 128 edges (4 queries each).
// Per tile: gather x rows (mask-skipped) -> As transposed [k][e], GEMM vs
// pre-duplicated w1 pairs (direct LDS.128 FFMA2 operand), + demb[delta],
// relu, masked per-query sums (deterministic smem reduce, no atomics).
// ---------------------------------------------------------------------------
__global__ void __launch_bounds__(256, 1)
its_edge_kernel(const float* __restrict__ x,
                const int* __restrict__ in_u,  const int* __restrict__ in_tau,
                const void* __restrict__ in_mask,
                const int* __restrict__ out_u, const int* __restrict__ out_tau,
                const void* __restrict__ out_mask,
                const int* __restrict__ times,
                const float* __restrict__ piw1, const float* __restrict__ pow1) {
    extern __shared__ char sm[];
    float* As    = (float*)(sm + EOFF_A);
    float* Bd    = (float*)(sm + EOFF_B);
    float* sdemb = (float*)(sm + EOFF_D);
    float* spart = (float*)(sm + EOFF_P);
    int* smask   = (int*)(sm + EOFF_M);
    int* sdelta  = smask + 128;
    int* srow    = sdelta + 128;

    int tid = threadIdx.x;
    int dir = (blockIdx.x >= EB) ? 1 : 0;
    int bslot = blockIdx.x - dir * EB;
    const int*  uu = dir ? out_u   : in_u;
    const int*  tt = dir ? out_tau : in_tau;
    const void* mm = dir ? out_mask : in_mask;
    const float* w1 = dir ? pow1 : piw1;
    int mode = g_mask_mode;

    // Stage duplicated w1 (once per block): Bd[k][2j..2j+1] = (w, w)
    for (int i = tid; i < 8192; i += 256) {
        int k = i >> 6, j = i & 63;
        float w = w1[i];
        Bd[k*128 + 2*j]     = w;
        Bd[k*128 + 2*j + 1] = w;
    }
    // Stage demb table (once per block)
    {
        const float4* dsrc = (const float4*)(g_demb + dir * 4160);
        float4* ddst = (float4*)sdemb;
        for (int i = tid; i < 1040; i += 256) ddst[i] = dsrc[i];
    }

    // Prefetch metadata for tile 0
    int pu = 0, pt = 0, pmk = 0, ptm = 0;
    {
        int tile0 = bslot * NTILE;
        if (tid < 128) {
            int s = tile0 * 128 + tid;
            pu  = uu[s];
            pt  = tt[s];
            pmk = read_mask(mm, s, mode);
            ptm = times[tile0 * 4 + (tid >> 5)];
        }
    }

    int g  = tid >> 4;        // 0..15: edge group (8 edges, one query per group of 4)
    int r0 = g * 8;
    int j0 = (tid & 15) * 4;

    for (int it = 0; it < NTILE; it++) {
        int tile = bslot * NTILE + it;

        // 1. publish metadata for this tile
        if (tid < 128) {
            int d = dir ? (pt - ptm) : (ptm - pt);
            d = d < 0 ? 0 : (d > WWIN ? WWIN : d);
            sdelta[tid] = d;
            srow[tid]   = pu * TT + pt;
            smask[tid]  = pmk;
        }
        __syncthreads();

        if (tid < 4) {
            int c = 0;
#pragma unroll
            for (int i = 0; i < 32; i++) c += smask[tid*32 + i];
            g_cnt[dir*QQ + tile*4 + tid] = c;
        }

        // 2. gather (mask-skipped) -> As transposed [k][e]
        {
            int e = tid >> 1, h = tid & 1;
            int valid = smask[e];
            const float4* xs = (const float4*)(x + (size_t)srow[e] * 128) + h * 16;
#pragma unroll
            for (int half = 0; half < 2; half++) {
                float4 buf[8];
#pragma unroll
                for (int gg = 0; gg < 8; gg++)
                    buf[gg] = valid ? xs[half*8 + gg] : make_float4(0.f, 0.f, 0.f, 0.f);
#pragma unroll
                for (int gg = 0; gg < 8; gg++) {
                    int k0 = h*64 + half*32 + gg*4;
                    As[(k0+0)*132 + e] = buf[gg].x;
                    As[(k0+1)*132 + e] = buf[gg].y;
                    As[(k0+2)*132 + e] = buf[gg].z;
                    As[(k0+3)*132 + e] = buf[gg].w;
                }
            }
        }

        // 3. prefetch metadata for next tile (hidden under the GEMM)
        if (it + 1 < NTILE && tid < 128) {
            int s = (tile + 1) * 128 + tid;
            pu  = uu[s];
            pt  = tt[s];
            pmk = read_mask(mm, s, mode);
            ptm = times[(tile + 1) * 4 + (tid >> 5)];
        }
        __syncthreads();

        // 4. GEMM: thread = 8 edges (4 FFMA2 pairs) x 4 j; B operand is a
        //    pre-duplicated (w,w) pair -> direct LDS.128, no MOVs.
        unsigned long long acc[4][4];
#pragma unroll
        for (int p = 0; p < 4; p++)
#pragma unroll
            for (int j = 0; j < 4; j++) acc[p][j] = 0ull;

#pragma unroll 8
        for (int k = 0; k < 128; k++) {
            const float* ar = As + k*132 + r0;
            ulonglong2 a01 = *(const ulonglong2*)ar;
            ulonglong2 a23 = *(const ulonglong2*)(ar + 4);
            const float* br = Bd + k*128 + j0*2;
            ulonglong2 b01 = *(const ulonglong2*)br;
            ulonglong2 b23 = *(const ulonglong2*)(br + 4);
            acc[0][0] = ffma2(a01.x, b01.x, acc[0][0]);
            acc[0][1] = ffma2(a01.x, b01.y, acc[0][1]);
            acc[0][2] = ffma2(a01.x, b23.x, acc[0][2]);
            acc[0][3] = ffma2(a01.x, b23.y, acc[0][3]);
            acc[1][0] = ffma2(a01.y, b01.x, acc[1][0]);
            acc[1][1] = ffma2(a01.y, b01.y, acc[1][1]);
            acc[1][2] = ffma2(a01.y, b23.x, acc[1][2]);
            acc[1][3] = ffma2(a01.y, b23.y, acc[1][3]);
            acc[2][0] = ffma2(a23.x, b01.x, acc[2][0]);
            acc[2][1] = ffma2(a23.x, b01.y, acc[2][1]);
            acc[2][2] = ffma2(a23.x, b23.x, acc[2][2]);
            acc[2][3] = ffma2(a23.x, b23.y, acc[2][3]);
            acc[3][0] = ffma2(a23.y, b01.x, acc[3][0]);
            acc[3][1] = ffma2(a23.y, b01.y, acc[3][1]);
            acc[3][2] = ffma2(a23.y, b23.x, acc[3][2]);
            acc[3][3] = ffma2(a23.y, b23.y, acc[3][3]);
        }

        // 5. epilogue: + demb[delta], relu, masked partial sums (8 edges, 1 query)
        float part[4] = {0.f, 0.f, 0.f, 0.f};
#pragma unroll
        for (int p = 0; p < 4; p++) {
            int e0 = r0 + 2*p, e1 = e0 + 1;
            float2 c0 = unpack2(acc[p][0]);
            float2 c1 = unpack2(acc[p][1]);
            float2 c2 = unpack2(acc[p][2]);
            float2 c3 = unpack2(acc[p][3]);
            if (smask[e0]) {
                const float4 dv = *(const float4*)(sdemb + sdelta[e0]*64 + j0);
                part[0] += fmaxf(c0.x + dv.x, 0.f);
                part[1] += fmaxf(c1.x + dv.y, 0.f);
                part[2] += fmaxf(c2.x + dv.z, 0.f);
                part[3] += fmaxf(c3.x + dv.w, 0.f);
            }
            if (smask[e1]) {
                const float4 dv = *(const float4*)(sdemb + sdelta[e1]*64 + j0);
                part[0] += fmaxf(c0.y + dv.x, 0.f);
                part[1] += fmaxf(c1.y + dv.y, 0.f);
                part[2] += fmaxf(c2.y + dv.z, 0.f);
                part[3] += fmaxf(c3.y + dv.w, 0.f);
            }
        }
        spart[g*64 + j0 + 0] = part[0];
        spart[g*64 + j0 + 1] = part[1];
        spart[g*64 + j0 + 2] = part[2];
        spart[g*64 + j0 + 3] = part[3];
        __syncthreads();

        // 6. deterministic reduce: 4 groups per query -> g_hsum
        {
            int q = tid >> 6, j = tid & 63;
            float s = spart[(q*4+0)*64 + j] + spart[(q*4+1)*64 + j]
                    + spart[(q*4+2)*64 + j] + spart[(q*4+3)*64 + j];
            g_hsum[(size_t)dir*QQ*64 + (size_t)(tile*4 + q)*64 + j] = s;
        }
        __syncthreads();
    }
}

// ---------------------------------------------------------------------------
// K3: per-query m_in/m_out (hsum @ w2 / cnt + b2) + x_vt gather -> g_feat[Q,256]
// Block = 24 queries, 256 threads (amortizes the w2 staging better than 16).
// ---------------------------------------------------------------------------
#define QT 24
__global__ void __launch_bounds__(256)
its_combine_a_kernel(const float* __restrict__ x,
                     const int* __restrict__ node_ids, const int* __restrict__ times,
                     const float* __restrict__ piw2, const float* __restrict__ pib2,
                     const float* __restrict__ pow2, const float* __restrict__ pob2) {
    __shared__ float s_w2[2*64*64];
    __shared__ float s_hs[2*QT*64];
    __shared__ float s_b2[2*64];
    __shared__ int   s_cnt[2*QT];

    int qb = blockIdx.x * QT;
    int tid = threadIdx.x;

    for (int i = tid; i < 4096; i += 256) {
        s_w2[i]        = piw2[i];
        s_w2[4096 + i] = pow2[i];
    }
    if (tid < 64) { s_b2[tid] = pib2[tid]; s_b2[64 + tid] = pob2[tid]; }
    for (int i = tid; i < QT*64; i += 256) {
        int qi = i >> 6, j = i & 63;
        s_hs[i]         = g_hsum[(size_t)(qb + qi)*64 + j];
        s_hs[QT*64 + i] = g_hsum[(size_t)QQ*64 + (size_t)(qb + qi)*64 + j];
    }
    if (tid < 2*QT) {
        int dir = tid >= QT, qi = tid - dir*QT;
        s_cnt[tid] = g_cnt[dir*QQ + qb + qi];
    }
    __syncthreads();

    // m = hsum @ w2 / max(cnt,1) + (cnt>0)*b2   (2*QT rows x 8 j-groups)
    for (int task = tid; task < 2*QT*8; task += 256) {
        int r = task >> 3, c = task & 7;
        int dir = r >= QT, qi = r - dir*QT;
        const float* hs = s_hs + dir*QT*64 + qi*64;
        const float* w2 = s_w2 + dir*4096;
        float acc[8] = {0,0,0,0,0,0,0,0};
#pragma unroll 8
        for (int k = 0; k < 64; k++) {
            float h = hs[k];
            const float* wr = w2 + k*64 + c*8;
            float4 w0 = *(const float4*)wr;
            float4 w1 = *(const float4*)(wr + 4);
            acc[0] += h*w0.x; acc[1] += h*w0.y; acc[2] += h*w0.z; acc[3] += h*w0.w;
            acc[4] += h*w1.x; acc[5] += h*w1.y; acc[6] += h*w1.z; acc[7] += h*w1.w;
        }
        int cnt = s_cnt[dir*QT + qi];
        float inv = 1.0f / (float)(cnt > 1 ? cnt : 1);
        float bsc = cnt > 0 ? 1.0f : 0.0f;
        float* dst = g_feat + (size_t)(qb + qi)*256 + 128 + dir*64 + c*8;
#pragma unroll
        for (int j = 0; j < 8; j++)
            dst[j] = acc[j]*inv + bsc * s_b2[dir*64 + c*8 + j];
    }

    // x_vt gather (QT q x 128 floats)
    for (int task = tid; task < QT*16; task += 256) {
        int qi = task >> 4, part = task & 15;
        int q = qb + qi;
        const float* src = x + (size_t)node_ids[q]*8192 + (size_t)times[q]*128 + part*8;
        float* dst = g_feat + (size_t)q*256 + part*8;
        float4 a = ((const float4*)src)[0];
        float4 b = ((const float4*)src)[1];
        ((float4*)dst)[0] = a;
        ((float4*)dst)[1] = b;
    }
}

// ---------------------------------------------------------------------------
// K4: u1 = relu(feat @ cw1 + cb1)   [Q,256]@[256,128]
// ---------------------------------------------------------------------------
__global__ void __launch_bounds__(256)
its_gemm1_kernel(const float* __restrict__ cw1, const float* __restrict__ cb1) {
    __shared__ float As[32*68];
    __shared__ float Bs[32*128];
    int qb = blockIdx.x * 64;
    int tid = threadIdx.x;
    int qg = (tid >> 4) * 4;
    int j0 = (tid & 15) * 8;

    unsigned long long acc[4][4];
#pragma unroll
    for (int a = 0; a < 4; a++)
#pragma unroll
        for (int b = 0; b < 4; b++) acc[a][b] = 0ull;

    for (int kc = 0; kc < 256; kc += 32) {
        {
            int q = tid >> 2, kq = tid & 3;
            const float* src = g_feat + (size_t)(qb + q)*256 + kc + kq*8;
            float4 v0 = ((const float4*)src)[0];
            float4 v1 = ((const float4*)src)[1];
            int k0 = kq*8;
            As[(k0+0)*68 + q] = v0.x; As[(k0+1)*68 + q] = v0.y;
            As[(k0+2)*68 + q] = v0.z; As[(k0+3)*68 + q] = v0.w;
            As[(k0+4)*68 + q] = v1.x; As[(k0+5)*68 + q] = v1.y;
            As[(k0+6)*68 + q] = v1.z; As[(k0+7)*68 + q] = v1.w;
        }
        {
            int k = tid >> 3, jb = (tid & 7) * 16;
            const float4* src = (const float4*)(cw1 + (size_t)(kc + k)*128 + jb);
            float4* dst = (float4*)(Bs + k*128 + jb);
            dst[0] = src[0]; dst[1] = src[1]; dst[2] = src[2]; dst[3] = src[3];
        }
        __syncthreads();
#pragma unroll
        for (int k = 0; k < 32; k++) {
            float4 av = *(const float4*)(As + k*68 + qg);
            ulonglong2 bA = *(const ulonglong2*)(Bs + k*128 + j0);
            ulonglong2 bB = *(const ulonglong2*)(Bs + k*128 + j0 + 4);
            unsigned long long a0 = dup2(av.x), a1 = dup2(av.y);
            unsigned long long a2 = dup2(av.z), a3 = dup2(av.w);
            acc[0][0] = ffma2(a0, bA.x, acc[0][0]); acc[0][1] = ffma2(a0, bA.y, acc[0][1]);
            acc[0][2] = ffma2(a0, bB.x, acc[0][2]); acc[0][3] = ffma2(a0, bB.y, acc[0][3]);
            acc[1][0] = ffma2(a1, bA.x, acc[1][0]); acc[1][1] = ffma2(a1, bA.y, acc[1][1]);
            acc[1][2] = ffma2(a1, bB.x, acc[1][2]); acc[1][3] = ffma2(a1, bB.y, acc[1][3]);
            acc[2][0] = ffma2(a2, bA.x, acc[2][0]); acc[2][1] = ffma2(a2, bA.y, acc[2][1]);
            acc[2][2] = ffma2(a2, bB.x, acc[2][2]); acc[2][3] = ffma2(a2, bB.y, acc[2][3]);
            acc[3][0] = ffma2(a3, bA.x, acc[3][0]); acc[3][1] = ffma2(a3, bA.y, acc[3][1]);
            acc[3][2] = ffma2(a3, bB.x, acc[3][2]); acc[3][3] = ffma2(a3, bB.y, acc[3][3]);
        }
        __syncthreads();
    }

#pragma unroll
    for (int jp = 0; jp < 4; jp++) {
        int j = j0 + jp*2;
        float b0 = cb1[j], b1 = cb1[j+1];
#pragma unroll
        for (int qi = 0; qi < 4; qi++) {
            float2 v = unpack2(acc[qi][jp]);
            float r0 = v.x + b0; r0 = r0 > 0.f ? r0 : 0.f;
            float r1 = v.y + b1; r1 = r1 > 0.f ? r1 : 0.f;
            float* dst = g_u1 + (size_t)(qb + qg + qi)*128 + j;
            dst[0] = r0; dst[1] = r1;
        }
    }
}

// ---------------------------------------------------------------------------
// K5: h = relu(u1 @ cw2 + cb2)  [Q,128]@[128,64] -> scatter into g_feat2
// ---------------------------------------------------------------------------
__global__ void __launch_bounds__(256)
its_gemm2_kernel(const float* __restrict__ cw2, const float* __restrict__ cb2) {
    __shared__ float As[32*68];
    __shared__ float Bs[32*64];
    int qb = blockIdx.x * 64;
    int tid = threadIdx.x;
    int qg = (tid >> 4) * 4;
    int j0 = (tid & 15) * 4;

    float acc[4][4];
#pragma unroll
    for (int a = 0; a < 4; a++)
#pragma unroll
        for (int b = 0; b < 4; b++) acc[a][b] = 0.f;

    for (int kc = 0; kc < 128; kc += 32) {
        {
            int q = tid >> 2, kq = tid & 3;
            const float* src = g_u1 + (size_t)(qb + q)*128 + kc + kq*8;
            float4 v0 = ((const float4*)src)[0];
            float4 v1 = ((const float4*)src)[1];
            int k0 = kq*8;
            As[(k0+0)*68 + q] = v0.x; As[(k0+1)*68 + q] = v0.y;
            As[(k0+2)*68 + q] = v0.z; As[(k0+3)*68 + q] = v0.w;
            As[(k0+4)*68 + q] = v1.x; As[(k0+5)*68 + q] = v1.y;
            As[(k0+6)*68 + q] = v1.z; As[(k0+7)*68 + q] = v1.w;
        }
        {
            int k = tid >> 3, jb = (tid & 7) * 8;
            const float4* src = (const float4*)(cw2 + (size_t)(kc + k)*64 + jb);
            float4* dst = (float4*)(Bs + k*64 + jb);
            dst[0] = src[0]; dst[1] = src[1];
        }
        __syncthreads();
#pragma unroll
        for (int k = 0; k < 32; k++) {
            float4 av = *(const float4*)(As + k*68 + qg);
            float4 bv = *(const float4*)(Bs + k*64 + j0);
            acc[0][0] += av.x*bv.x; acc[0][1] += av.x*bv.y; acc[0][2] += av.x*bv.z; acc[0][3] += av.x*bv.w;
            acc[1][0] += av.y*bv.x; acc[1][1] += av.y*bv.y; acc[1][2] += av.y*bv.z; acc[1][3] += av.y*bv.w;
            acc[2][0] += av.z*bv.x; acc[2][1] += av.z*bv.y; acc[2][2] += av.z*bv.z; acc[2][3] += av.z*bv.w;
            acc[3][0] += av.w*bv.x; acc[3][1] += av.w*bv.y; acc[3][2] += av.w*bv.z; acc[3][3] += av.w*bv.w;
        }
        __syncthreads();
    }

#pragma unroll
    for (int qi = 0; qi < 4; qi++) {
        int gq = qb + qg + qi;
        int bb = gq / 3;
        int slot = gq - bb*3;
        float* dst = g_feat2 + (size_t)bb*193 + slot*64 + j0;
#pragma unroll
        for (int j = 0; j < 4; j++) {
            float h = acc[qi][j] + cb2[j0 + j];
            dst[j] = h > 0.f ? h : 0.f;
        }
    }
}

// ---------------------------------------------------------------------------
// K6: out[b] = relu(feat2 @ sw1 + sb1) @ sw2 + sb2   (warp per b)
// ---------------------------------------------------------------------------
__global__ void __launch_bounds__(256)
its_score_kernel(const float* __restrict__ sw1, const float* __restrict__ sb1,
                 const float* __restrict__ sw2, const float* __restrict__ sb2,
                 const float* __restrict__ d_norm, float* __restrict__ out) {
    __shared__ float srow[8*200];
    int tid = threadIdx.x;
    int w = tid >> 5, lane = tid & 31;
    int b = blockIdx.x * 8 + w;

    for (int k = lane; k < 192; k += 32)
        srow[w*200 + k] = g_feat2[(size_t)b*193 + k];
    if (lane == 0) srow[w*200 + 192] = d_norm[b];
    __syncwarp();

    float a0 = 0.f, a1 = 0.f, a2 = 0.f, a3 = 0.f;
    for (int k = 0; k < 193; k++) {
        float f = srow[w*200 + k];
        float4 wv = *(const float4*)(sw1 + (size_t)k*128 + lane*4);
        a0 += f*wv.x; a1 += f*wv.y; a2 += f*wv.z; a3 += f*wv.w;
    }
    int j = lane * 4;
    float v0 = a0 + sb1[j+0]; v0 = v0 > 0.f ? v0 : 0.f;
    float v1 = a1 + sb1[j+1]; v1 = v1 > 0.f ? v1 : 0.f;
    float v2 = a2 + sb1[j+2]; v2 = v2 > 0.f ? v2 : 0.f;
    float v3 = a3 + sb1[j+3]; v3 = v3 > 0.f ? v3 : 0.f;
    float4 w2v = *(const float4*)(sw2 + j);
    float p = v0*w2v.x + v1*w2v.y + v2*w2v.z + v3*w2v.w;
#pragma unroll
    for (int off = 16; off > 0; off >>= 1)
        p += __shfl_xor_sync(0xffffffffu, p, off);
    if (lane == 0) out[b] = p + sb2[0];
}

// ---------------------------------------------------------------------------
// kernel_launch
// ---------------------------------------------------------------------------
extern "C" void kernel_launch(void* const* d_in, const int* in_sizes, int n_in,
                              void* d_out, int out_size) {
    const float* x       = (const float*)d_in[0];
    const float* d_norm  = (const float*)d_in[1];
    const float* demb    = (const float*)d_in[2];
    const float* piw1    = (const float*)d_in[3];
    const float* pib1    = (const float*)d_in[4];
    const float* piw2    = (const float*)d_in[5];
    const float* pib2    = (const float*)d_in[6];
    const float* pow1    = (const float*)d_in[7];
    const float* pob1    = (const float*)d_in[8];
    const float* pow2    = (const float*)d_in[9];
    const float* pob2    = (const float*)d_in[10];
    const float* cw1     = (const float*)d_in[11];
    const float* cb1     = (const float*)d_in[12];
    const float* cw2     = (const float*)d_in[13];
    const float* cb2     = (const float*)d_in[14];
    const float* sw1     = (const float*)d_in[15];
    const float* sb1     = (const float*)d_in[16];
    const float* sw2     = (const float*)d_in[17];
    const float* sb2     = (const float*)d_in[18];
    const int* node_ids  = (const int*)d_in[19];
    const int* times     = (const int*)d_in[20];
    const int* in_u      = (const int*)d_in[21];
    const int* in_tau    = (const int*)d_in[22];
    const void* in_mask  = d_in[23];
    const int* out_u     = (const int*)d_in[24];
    const int* out_tau   = (const int*)d_in[25];
    const void* out_mask = d_in[26];
    float* out = (float*)d_out;

    cudaFuncSetAttribute(its_edge_kernel,
                         cudaFuncAttributeMaxDynamicSharedMemorySize, SMEM_EK);

    its_detect_kernel<<<1, 256>>>((const unsigned int*)in_mask);
    its_tables_kernel<<<2, 256>>>(demb, piw1, pib1, pow1, pob1);
    its_edge_kernel<<<2*EB, 256, SMEM_EK>>>(x,
        in_u, in_tau, in_mask, out_u, out_tau, out_mask, times, piw1, pow1);
    its_combine_a_kernel<<<QQ/QT, 256>>>(x, node_ids, times, piw2, pib2, pow2, pob2);
    its_gemm1_kernel<<<QQ/64, 256>>>(cw1, cb1);
    its_gemm2_kernel<<<QQ/64, 256>>>(cw2, cb2);
    its_score_kernel<<<BB/8, 256>>>(sw1, sb1, sw2, sb2, d_norm, out);
}

// round 12
// speedup vs baseline: 1.3509x; 1.3509x over previous
#include <cuda_runtime.h>
#include <cuda_bf16.h>
#include <cstdint>

// ---------------------------------------------------------------------------
// Problem constants
// ---------------------------------------------------------------------------
#define NN      20000
#define TT      64
#define FF      128
#define BB      8192
#define KK      32
#define QQ      (3*BB)            // 24576
#define WWIN    64
#define QK      (QQ*KK)           // 786432
#define TILE_E  64                // edges per block (= 2 full queries)
#define TILES2  (QK/TILE_E)       // 12288 tiles per direction

// Edge-kernel dynamic smem (floats): As[128][68] | Bs[128][68] | spart[16][64] | meta
#define SMEM_EK ((128*68 + 128*68 + 16*64 + 192) * 4)   // 74496 B -> occupancy 3

// Score-kernel dynamic smem (floats): s_w1[193*128] | srow[8][200]
#define SMEM_SC ((193*128 + 8*200) * 4)                 // 105216 B

// ---------------------------------------------------------------------------
// Device scratch (static __device__ arrays — allocation APIs are forbidden)
// ---------------------------------------------------------------------------
__device__ int    g_mask_mode;                // 0=u8, 1=i32, 2=f32
__device__ float  g_demb[2*65*64];            // per-dir (delta_emb@w1_delta + b1)
__device__ float  g_hsum[2*(size_t)QQ*64];    // per-(dir,query) sum of relu hidden
__device__ int    g_cnt[2*QQ];                // per-(dir,query) valid-edge count
__device__ float  g_feat[(size_t)QQ*256];     // [x_vt | m_in | m_out]
__device__ float  g_u1[(size_t)QQ*128];       // combine hidden 1
__device__ float  g_feat2[(size_t)BB*193];    // scorer features

// ---------------------------------------------------------------------------
// f32x2 helpers (sm_103a packed fp32 — 2x FFMA throughput)
// ---------------------------------------------------------------------------
__device__ __forceinline__ unsigned long long ffma2(unsigned long long a,
                                                    unsigned long long b,
                                                    unsigned long long c) {
    unsigned long long d;
    asm("fma.rn.f32x2 %0, %1, %2, %3;" : "=l"(d) : "l"(a), "l"(b), "l"(c));
    return d;
}
__device__ __forceinline__ unsigned long long dup2(float v) {
    unsigned long long r;
    asm("mov.b64 %0, {%1, %2};" : "=l"(r) : "f"(v), "f"(v));
    return r;
}
__device__ __forceinline__ float2 unpack2(unsigned long long v) {
    float2 r;
    asm("mov.b64 {%0, %1}, %2;" : "=f"(r.x), "=f"(r.y) : "l"(v));
    return r;
}
__device__ __forceinline__ int read_mask(const void* p, int idx, int mode) {
    if (mode == 1) return ((const int*)p)[idx] != 0;
    if (mode == 2) return ((const float*)p)[idx] != 0.0f;
    return ((const unsigned char*)p)[idx] != 0;
}

// ---------------------------------------------------------------------------
// K0: classify mask serialization (u8 / i32 / f32)
// ---------------------------------------------------------------------------
__global__ void its_detect_kernel(const unsigned int* __restrict__ m) {
    __shared__ int not01, not0f;
    if (threadIdx.x == 0) { not01 = 0; not0f = 0; }
    __syncthreads();
    int l01 = 0, l0f = 0;
    for (int i = threadIdx.x; i < QK/4; i += blockDim.x) {
        unsigned v = m[i];
        if (v > 1u) l01 = 1;
        if (v != 0u && v != 0x3F800000u) l0f = 1;
    }
    if (l01) not01 = 1;
    if (l0f) not0f = 1;
    __syncthreads();
    if (threadIdx.x == 0)
        g_mask_mode = (!not01) ? 1 : ((!not0f) ? 2 : 0);
}

// ---------------------------------------------------------------------------
// K1: delta tables: g_demb[dir][d][j] = delta_emb[d] @ w1[128:144, :] + b1[j]
// ---------------------------------------------------------------------------
__global__ void its_tables_kernel(const float* __restrict__ demb,
                                  const float* __restrict__ piw1, const float* __restrict__ pib1,
                                  const float* __restrict__ pow1, const float* __restrict__ pob1) {
    int dir = blockIdx.x;
    const float* w1 = dir ? pow1 : piw1;
    const float* b1 = dir ? pob1 : pib1;
    float* out = g_demb + dir * (65*64);
    for (int idx = threadIdx.x; idx < 65*64; idx += blockDim.x) {
        int d = idx >> 6, j = idx & 63;
        float acc = b1[j];
#pragma unroll
        for (int dd = 0; dd < 16; dd++)
            acc += demb[d*16 + dd] * w1[(128 + dd)*64 + j];
        out[idx] = acc;
    }
}

// ---------------------------------------------------------------------------
// K2: edge aggregation (proven R6 skeleton, occupancy 3, demb via L1).
// One block = one direction x 64 edge slots (2 queries).
// Gather x rows -> smem transposed [k][e], FFMA2 GEMM vs w1[:128] -> z,
// + g_demb[delta] (global, L1-hot), relu, masked per-query sums.
// ---------------------------------------------------------------------------
__global__ void __launch_bounds__(256, 3)
its_edge_kernel(const float* __restrict__ x,
                const int* __restrict__ in_u,  const int* __restrict__ in_tau,
                const void* __restrict__ in_mask,
                const int* __restrict__ out_u, const int* __restrict__ out_tau,
                const void* __restrict__ out_mask,
                const int* __restrict__ times,
                const float* __restrict__ piw1, const float* __restrict__ pow1) {
    extern __shared__ float sm[];
    float* As    = sm;               // [128 k][68]  (64 edges + pad)
    float* Bs    = As + 128*68;      // [128 k][68]  (64 j + pad)
    float* spart = Bs + 128*68;      // [16 groups][64]
    int* sdelta  = (int*)(spart + 16*64);  // [64]
    int* srow    = sdelta + 64;            // [64]
    int* smask   = srow + 64;              // [64]

    int bid  = blockIdx.x;
    int dir  = (bid >= TILES2) ? 1 : 0;
    int tile = bid - dir * TILES2;
    const int*  uu = dir ? out_u   : in_u;
    const int*  tt = dir ? out_tau : in_tau;
    const void* mm = dir ? out_mask : in_mask;
    const float* w1 = dir ? pow1 : piw1;
    const float* gdemb = g_demb + dir * 4160;
    int tid = threadIdx.x;
    int mode = g_mask_mode;

    // Stage w1 rows 0..127 (8192 floats)
    for (int i = tid; i < 2048; i += 256) {
        float4 v = ((const float4*)w1)[i];
        int k = i >> 4, j = (i & 15) * 4;
        *(float4*)(Bs + k*68 + j) = v;
    }

    // Edge metadata
    if (tid < 64) {
        int e = tid;
        int s = tile*TILE_E + e;
        int q = s >> 5;
        int t = times[q];
        int u = uu[s], ta = tt[s];
        int d = dir ? (ta - t) : (t - ta);
        d = d < 0 ? 0 : (d > WWIN ? WWIN : d);
        sdelta[e] = d;
        srow[e]   = u*TT + ta;
        smask[e]  = read_mask(mm, s, mode);
    }
    __syncthreads();

    // Valid-edge counts
    if (tid < 2) {
        int c = 0;
#pragma unroll
        for (int i = 0; i < 32; i++) c += smask[tid*32 + i];
        g_cnt[dir*QQ + tile*2 + tid] = c;
    }

    // Gather x rows -> As transposed [k][e]; zero masked-out edges
    {
        int e = tid >> 2, h = tid & 3;
        if (smask[e]) {
            const float4* src = (const float4*)(x + (size_t)srow[e]*128) + h*8;
#pragma unroll
            for (int i = 0; i < 8; i++) {
                float4 v = src[i];
                int k0 = h*32 + i*4;
                As[(k0+0)*68 + e] = v.x;
                As[(k0+1)*68 + e] = v.y;
                As[(k0+2)*68 + e] = v.z;
                As[(k0+3)*68 + e] = v.w;
            }
        } else {
#pragma unroll
            for (int i = 0; i < 8; i++) {
                int k0 = h*32 + i*4;
                As[(k0+0)*68 + e] = 0.0f;
                As[(k0+1)*68 + e] = 0.0f;
                As[(k0+2)*68 + e] = 0.0f;
                As[(k0+3)*68 + e] = 0.0f;
            }
        }
    }
    __syncthreads();

    // GEMM: thread = 4 edges (2 FFMA2 pairs) x 4 j
    int r0 = (tid >> 4) * 4;     // edge base (within one query)
    int o0 = (tid & 15) * 4;     // j base
    unsigned long long acc[2][4];
#pragma unroll
    for (int p = 0; p < 2; p++)
#pragma unroll
        for (int j = 0; j < 4; j++) acc[p][j] = 0ull;

#pragma unroll 8
    for (int k = 0; k < 128; k++) {
        ulonglong2 a = *(const ulonglong2*)(As + k*68 + r0);
        float4 bv = *(const float4*)(Bs + k*68 + o0);
        unsigned long long b0 = dup2(bv.x), b1 = dup2(bv.y);
        unsigned long long b2 = dup2(bv.z), b3 = dup2(bv.w);
        acc[0][0] = ffma2(a.x, b0, acc[0][0]);
        acc[0][1] = ffma2(a.x, b1, acc[0][1]);
        acc[0][2] = ffma2(a.x, b2, acc[0][2]);
        acc[0][3] = ffma2(a.x, b3, acc[0][3]);
        acc[1][0] = ffma2(a.y, b0, acc[1][0]);
        acc[1][1] = ffma2(a.y, b1, acc[1][1]);
        acc[1][2] = ffma2(a.y, b2, acc[1][2]);
        acc[1][3] = ffma2(a.y, b3, acc[1][3]);
    }

    // + demb[delta] (global, L1-hot), relu, masked partial sums
    float part[4] = {0.f, 0.f, 0.f, 0.f};
#pragma unroll
    for (int p = 0; p < 2; p++) {
        int e0 = r0 + 2*p, e1 = e0 + 1;
        float2 c0 = unpack2(acc[p][0]);
        float2 c1 = unpack2(acc[p][1]);
        float2 c2 = unpack2(acc[p][2]);
        float2 c3 = unpack2(acc[p][3]);
        if (smask[e0]) {
            float4 dv = *(const float4*)(gdemb + sdelta[e0]*64 + o0);
            part[0] += fmaxf(c0.x + dv.x, 0.f);
            part[1] += fmaxf(c1.x + dv.y, 0.f);
            part[2] += fmaxf(c2.x + dv.z, 0.f);
            part[3] += fmaxf(c3.x + dv.w, 0.f);
        }
        if (smask[e1]) {
            float4 dv = *(const float4*)(gdemb + sdelta[e1]*64 + o0);
            part[0] += fmaxf(c0.y + dv.x, 0.f);
            part[1] += fmaxf(c1.y + dv.y, 0.f);
            part[2] += fmaxf(c2.y + dv.z, 0.f);
            part[3] += fmaxf(c3.y + dv.w, 0.f);
        }
    }
    int te = tid >> 4;
    spart[te*64 + o0 + 0] = part[0];
    spart[te*64 + o0 + 1] = part[1];
    spart[te*64 + o0 + 2] = part[2];
    spart[te*64 + o0 + 3] = part[3];
    __syncthreads();

    // Deterministic reduce: 8 groups per query
    if (tid < 128) {
        int q = tid >> 6, j = tid & 63;
        float s = 0.f;
#pragma unroll
        for (int g = 0; g < 8; g++) s += spart[(q*8 + g)*64 + j];
        g_hsum[(size_t)dir*QQ*64 + (size_t)(tile*2 + q)*64 + j] = s;
    }
}

// ---------------------------------------------------------------------------
// K3: per-query m_in/m_out (hsum @ w2 / cnt + b2) + x_vt gather -> g_feat[Q,256]
// ---------------------------------------------------------------------------
#define QT 24
__global__ void __launch_bounds__(256)
its_combine_a_kernel(const float* __restrict__ x,
                     const int* __restrict__ node_ids, const int* __restrict__ times,
                     const float* __restrict__ piw2, const float* __restrict__ pib2,
                     const float* __restrict__ pow2, const float* __restrict__ pob2) {
    __shared__ float s_w2[2*64*64];
    __shared__ float s_hs[2*QT*64];
    __shared__ float s_b2[2*64];
    __shared__ int   s_cnt[2*QT];

    int qb = blockIdx.x * QT;
    int tid = threadIdx.x;

    for (int i = tid; i < 4096; i += 256) {
        s_w2[i]        = piw2[i];
        s_w2[4096 + i] = pow2[i];
    }
    if (tid < 64) { s_b2[tid] = pib2[tid]; s_b2[64 + tid] = pob2[tid]; }
    for (int i = tid; i < QT*64; i += 256) {
        int qi = i >> 6, j = i & 63;
        s_hs[i]         = g_hsum[(size_t)(qb + qi)*64 + j];
        s_hs[QT*64 + i] = g_hsum[(size_t)QQ*64 + (size_t)(qb + qi)*64 + j];
    }
    if (tid < 2*QT) {
        int dir = tid >= QT, qi = tid - dir*QT;
        s_cnt[tid] = g_cnt[dir*QQ + qb + qi];
    }
    __syncthreads();

    for (int task = tid; task < 2*QT*8; task += 256) {
        int r = task >> 3, c = task & 7;
        int dir = r >= QT, qi = r - dir*QT;
        const float* hs = s_hs + dir*QT*64 + qi*64;
        const float* w2 = s_w2 + dir*4096;
        float acc[8] = {0,0,0,0,0,0,0,0};
#pragma unroll 8
        for (int k = 0; k < 64; k++) {
            float h = hs[k];
            const float* wr = w2 + k*64 + c*8;
            float4 w0 = *(const float4*)wr;
            float4 w1 = *(const float4*)(wr + 4);
            acc[0] += h*w0.x; acc[1] += h*w0.y; acc[2] += h*w0.z; acc[3] += h*w0.w;
            acc[4] += h*w1.x; acc[5] += h*w1.y; acc[6] += h*w1.z; acc[7] += h*w1.w;
        }
        int cnt = s_cnt[dir*QT + qi];
        float inv = 1.0f / (float)(cnt > 1 ? cnt : 1);
        float bsc = cnt > 0 ? 1.0f : 0.0f;
        float* dst = g_feat + (size_t)(qb + qi)*256 + 128 + dir*64 + c*8;
#pragma unroll
        for (int j = 0; j < 8; j++)
            dst[j] = acc[j]*inv + bsc * s_b2[dir*64 + c*8 + j];
    }

    for (int task = tid; task < QT*16; task += 256) {
        int qi = task >> 4, part = task & 15;
        int q = qb + qi;
        const float* src = x + (size_t)node_ids[q]*8192 + (size_t)times[q]*128 + part*8;
        float* dst = g_feat + (size_t)q*256 + part*8;
        float4 a = ((const float4*)src)[0];
        float4 b = ((const float4*)src)[1];
        ((float4*)dst)[0] = a;
        ((float4*)dst)[1] = b;
    }
}

// ---------------------------------------------------------------------------
// K4: u1 = relu(feat @ cw1 + cb1)   [Q,256]@[256,128]
// ---------------------------------------------------------------------------
__global__ void __launch_bounds__(256)
its_gemm1_kernel(const float* __restrict__ cw1, const float* __restrict__ cb1) {
    __shared__ float As[32*68];
    __shared__ float Bs[32*128];
    int qb = blockIdx.x * 64;
    int tid = threadIdx.x;
    int qg = (tid >> 4) * 4;
    int j0 = (tid & 15) * 8;

    unsigned long long acc[4][4];
#pragma unroll
    for (int a = 0; a < 4; a++)
#pragma unroll
        for (int b = 0; b < 4; b++) acc[a][b] = 0ull;

    for (int kc = 0; kc < 256; kc += 32) {
        {
            int q = tid >> 2, kq = tid & 3;
            const float* src = g_feat + (size_t)(qb + q)*256 + kc + kq*8;
            float4 v0 = ((const float4*)src)[0];
            float4 v1 = ((const float4*)src)[1];
            int k0 = kq*8;
            As[(k0+0)*68 + q] = v0.x; As[(k0+1)*68 + q] = v0.y;
            As[(k0+2)*68 + q] = v0.z; As[(k0+3)*68 + q] = v0.w;
            As[(k0+4)*68 + q] = v1.x; As[(k0+5)*68 + q] = v1.y;
            As[(k0+6)*68 + q] = v1.z; As[(k0+7)*68 + q] = v1.w;
        }
        {
            int k = tid >> 3, jb = (tid & 7) * 16;
            const float4* src = (const float4*)(cw1 + (size_t)(kc + k)*128 + jb);
            float4* dst = (float4*)(Bs + k*128 + jb);
            dst[0] = src[0]; dst[1] = src[1]; dst[2] = src[2]; dst[3] = src[3];
        }
        __syncthreads();
#pragma unroll
        for (int k = 0; k < 32; k++) {
            float4 av = *(const float4*)(As + k*68 + qg);
            ulonglong2 bA = *(const ulonglong2*)(Bs + k*128 + j0);
            ulonglong2 bB = *(const ulonglong2*)(Bs + k*128 + j0 + 4);
            unsigned long long a0 = dup2(av.x), a1 = dup2(av.y);
            unsigned long long a2 = dup2(av.z), a3 = dup2(av.w);
            acc[0][0] = ffma2(a0, bA.x, acc[0][0]); acc[0][1] = ffma2(a0, bA.y, acc[0][1]);
            acc[0][2] = ffma2(a0, bB.x, acc[0][2]); acc[0][3] = ffma2(a0, bB.y, acc[0][3]);
            acc[1][0] = ffma2(a1, bA.x, acc[1][0]); acc[1][1] = ffma2(a1, bA.y, acc[1][1]);
            acc[1][2] = ffma2(a1, bB.x, acc[1][2]); acc[1][3] = ffma2(a1, bB.y, acc[1][3]);
            acc[2][0] = ffma2(a2, bA.x, acc[2][0]); acc[2][1] = ffma2(a2, bA.y, acc[2][1]);
            acc[2][2] = ffma2(a2, bB.x, acc[2][2]); acc[2][3] = ffma2(a2, bB.y, acc[2][3]);
            acc[3][0] = ffma2(a3, bA.x, acc[3][0]); acc[3][1] = ffma2(a3, bA.y, acc[3][1]);
            acc[3][2] = ffma2(a3, bB.x, acc[3][2]); acc[3][3] = ffma2(a3, bB.y, acc[3][3]);
        }
        __syncthreads();
    }

#pragma unroll
    for (int jp = 0; jp < 4; jp++) {
        int j = j0 + jp*2;
        float b0 = cb1[j], b1 = cb1[j+1];
#pragma unroll
        for (int qi = 0; qi < 4; qi++) {
            float2 v = unpack2(acc[qi][jp]);
            float r0 = v.x + b0; r0 = r0 > 0.f ? r0 : 0.f;
            float r1 = v.y + b1; r1 = r1 > 0.f ? r1 : 0.f;
            float* dst = g_u1 + (size_t)(qb + qg + qi)*128 + j;
            dst[0] = r0; dst[1] = r1;
        }
    }
}

// ---------------------------------------------------------------------------
// K5: h = relu(u1 @ cw2 + cb2)  [Q,128]@[128,64] -> scatter into g_feat2
// ---------------------------------------------------------------------------
__global__ void __launch_bounds__(256)
its_gemm2_kernel(const float* __restrict__ cw2, const float* __restrict__ cb2) {
    __shared__ float As[32*68];
    __shared__ float Bs[32*64];
    int qb = blockIdx.x * 64;
    int tid = threadIdx.x;
    int qg = (tid >> 4) * 4;
    int j0 = (tid & 15) * 4;

    float acc[4][4];
#pragma unroll
    for (int a = 0; a < 4; a++)
#pragma unroll
        for (int b = 0; b < 4; b++) acc[a][b] = 0.f;

    for (int kc = 0; kc < 128; kc += 32) {
        {
            int q = tid >> 2, kq = tid & 3;
            const float* src = g_u1 + (size_t)(qb + q)*128 + kc + kq*8;
            float4 v0 = ((const float4*)src)[0];
            float4 v1 = ((const float4*)src)[1];
            int k0 = kq*8;
            As[(k0+0)*68 + q] = v0.x; As[(k0+1)*68 + q] = v0.y;
            As[(k0+2)*68 + q] = v0.z; As[(k0+3)*68 + q] = v0.w;
            As[(k0+4)*68 + q] = v1.x; As[(k0+5)*68 + q] = v1.y;
            As[(k0+6)*68 + q] = v1.z; As[(k0+7)*68 + q] = v1.w;
        }
        {
            int k = tid >> 3, jb = (tid & 7) * 8;
            const float4* src = (const float4*)(cw2 + (size_t)(kc + k)*64 + jb);
            float4* dst = (float4*)(Bs + k*64 + jb);
            dst[0] = src[0]; dst[1] = src[1];
        }
        __syncthreads();
#pragma unroll
        for (int k = 0; k < 32; k++) {
            float4 av = *(const float4*)(As + k*68 + qg);
            float4 bv = *(const float4*)(Bs + k*64 + j0);
            acc[0][0] += av.x*bv.x; acc[0][1] += av.x*bv.y; acc[0][2] += av.x*bv.z; acc[0][3] += av.x*bv.w;
            acc[1][0] += av.y*bv.x; acc[1][1] += av.y*bv.y; acc[1][2] += av.y*bv.z; acc[1][3] += av.y*bv.w;
            acc[2][0] += av.z*bv.x; acc[2][1] += av.z*bv.y; acc[2][2] += av.z*bv.z; acc[2][3] += av.z*bv.w;
            acc[3][0] += av.w*bv.x; acc[3][1] += av.w*bv.y; acc[3][2] += av.w*bv.z; acc[3][3] += av.w*bv.w;
        }
        __syncthreads();
    }

#pragma unroll
    for (int qi = 0; qi < 4; qi++) {
        int gq = qb + qg + qi;
        int bb = gq / 3;
        int slot = gq - bb*3;
        float* dst = g_feat2 + (size_t)bb*193 + slot*64 + j0;
#pragma unroll
        for (int j = 0; j < 4; j++) {
            float h = acc[qi][j] + cb2[j0 + j];
            dst[j] = h > 0.f ? h : 0.f;
        }
    }
}

// ---------------------------------------------------------------------------
// K6: out[b] = relu(feat2 @ sw1 + sb1) @ sw2 + sb2
// Block = 32 b; sw1 (99KB) staged ONCE per block in dynamic smem.
// ---------------------------------------------------------------------------
__global__ void __launch_bounds__(256)
its_score_kernel(const float* __restrict__ sw1, const float* __restrict__ sb1,
                 const float* __restrict__ sw2, const float* __restrict__ sb2,
                 const float* __restrict__ d_norm, float* __restrict__ out) {
    extern __shared__ float smsc[];
    float* s_w1 = smsc;              // [193*128]
    float* srow = smsc + 24704;      // [8][200]
    int tid = threadIdx.x;
    int w = tid >> 5, lane = tid & 31;

    for (int i = tid; i < 6176; i += 256)
        ((float4*)s_w1)[i] = ((const float4*)sw1)[i];
    __syncthreads();

    float4 w2v = *(const float4*)(sw2 + lane*4);
    float sbias = sb2[0];
    float b1v0 = sb1[lane*4+0], b1v1 = sb1[lane*4+1];
    float b1v2 = sb1[lane*4+2], b1v3 = sb1[lane*4+3];

#pragma unroll
    for (int sub = 0; sub < 4; sub++) {
        int b = blockIdx.x * 32 + w * 4 + sub;
        for (int k = lane; k < 192; k += 32)
            srow[w*200 + k] = g_feat2[(size_t)b*193 + k];
        if (lane == 0) srow[w*200 + 192] = d_norm[b];
        __syncwarp();

        float a0 = 0.f, a1 = 0.f, a2 = 0.f, a3 = 0.f;
        for (int k = 0; k < 193; k++) {
            float f = srow[w*200 + k];
            float4 wv = *(const float4*)(s_w1 + k*128 + lane*4);
            a0 += f*wv.x; a1 += f*wv.y; a2 += f*wv.z; a3 += f*wv.w;
        }
        float v0 = fmaxf(a0 + b1v0, 0.f);
        float v1 = fmaxf(a1 + b1v1, 0.f);
        float v2 = fmaxf(a2 + b1v2, 0.f);
        float v3 = fmaxf(a3 + b1v3, 0.f);
        float p = v0*w2v.x + v1*w2v.y + v2*w2v.z + v3*w2v.w;
#pragma unroll
        for (int off = 16; off > 0; off >>= 1)
            p += __shfl_xor_sync(0xffffffffu, p, off);
        if (lane == 0) out[b] = p + sbias;
        __syncwarp();
    }
}

// ---------------------------------------------------------------------------
// kernel_launch
// ---------------------------------------------------------------------------
extern "C" void kernel_launch(void* const* d_in, const int* in_sizes, int n_in,
                              void* d_out, int out_size) {
    const float* x       = (const float*)d_in[0];
    const float* d_norm  = (const float*)d_in[1];
    const float* demb    = (const float*)d_in[2];
    const float* piw1    = (const float*)d_in[3];
    const float* pib1    = (const float*)d_in[4];
    const float* piw2    = (const float*)d_in[5];
    const float* pib2    = (const float*)d_in[6];
    const float* pow1    = (const float*)d_in[7];
    const float* pob1    = (const float*)d_in[8];
    const float* pow2    = (const float*)d_in[9];
    const float* pob2    = (const float*)d_in[10];
    const float* cw1     = (const float*)d_in[11];
    const float* cb1     = (const float*)d_in[12];
    const float* cw2     = (const float*)d_in[13];
    const float* cb2     = (const float*)d_in[14];
    const float* sw1     = (const float*)d_in[15];
    const float* sb1     = (const float*)d_in[16];
    const float* sw2     = (const float*)d_in[17];
    const float* sb2     = (const float*)d_in[18];
    const int* node_ids  = (const int*)d_in[19];
    const int* times     = (const int*)d_in[20];
    const int* in_u      = (const int*)d_in[21];
    const int* in_tau    = (const int*)d_in[22];
    const void* in_mask  = d_in[23];
    const int* out_u     = (const int*)d_in[24];
    const int* out_tau   = (const int*)d_in[25];
    const void* out_mask = d_in[26];
    float* out = (float*)d_out;

    cudaFuncSetAttribute(its_edge_kernel,
                         cudaFuncAttributeMaxDynamicSharedMemorySize, SMEM_EK);
    cudaFuncSetAttribute(its_score_kernel,
                         cudaFuncAttributeMaxDynamicSharedMemorySize, SMEM_SC);

    its_detect_kernel<<<1, 256>>>((const unsigned int*)in_mask);
    its_tables_kernel<<<2, 256>>>(demb, piw1, pib1, pow1, pob1);
    its_edge_kernel<<<2*TILES2, 256, SMEM_EK>>>(x,
        in_u, in_tau, in_mask, out_u, out_tau, out_mask, times, piw1, pow1);
    its_combine_a_kernel<<<QQ/QT, 256>>>(x, node_ids, times, piw2, pib2, pow2, pob2);
    its_gemm1_kernel<<<QQ/64, 256>>>(cw1, cb1);
    its_gemm2_kernel<<<QQ/64, 256>>>(cw2, cb2);
    its_score_kernel<<<BB/32, 256, SMEM_SC>>>(sw1, sb1, sw2, sb2, d_norm, out);
}

// round 13
// speedup vs baseline: 1.6787x; 1.2427x over previous
#include <cuda_runtime.h>
#include <cuda_bf16.h>
#include <cstdint>

// ---------------------------------------------------------------------------
// Problem constants
// ---------------------------------------------------------------------------
#define NN      20000
#define TT      64
#define FF      128
#define BB      8192
#define KK      32
#define QQ      (3*BB)            // 24576
#define WWIN    64
#define QK      (QQ*KK)           // 786432
#define TILE_E  64                // edges per block (= 2 full queries)
#define TILES2  (QK/TILE_E)       // 12288 tiles per direction

// Edge-kernel dynamic smem (floats): As[128][68] | Bs[128][68] | spart[16][64] | meta(192)
#define SMEM_EK ((128*68 + 128*68 + 16*64 + 192) * 4)   // 74496 B -> occupancy 3

// Score-kernel dynamic smem (floats): s_w1[193*128] | srow[8][200]
#define SMEM_SC ((193*128 + 8*200) * 4)                 // 105216 B

// ---------------------------------------------------------------------------
// Device scratch (static __device__ arrays — allocation APIs are forbidden)
// ---------------------------------------------------------------------------
__device__ int    g_mask_mode;                // 0=u8, 1=i32, 2=f32
__device__ float  g_demb[2*65*64];            // per-dir (delta_emb@w1_delta + b1)
__device__ float  g_hsum[2*(size_t)QQ*64];    // per-(dir,query) sum of relu hidden
__device__ int    g_cnt[2*QQ];                // per-(dir,query) valid-edge count
__device__ float  g_feat[(size_t)QQ*256];     // [x_vt | m_in | m_out]
__device__ float  g_u1[(size_t)QQ*128];       // combine hidden 1
__device__ float  g_feat2[(size_t)BB*193];    // scorer features

// ---------------------------------------------------------------------------
// f32x2 helpers (sm_103a packed fp32 — 2x FFMA throughput)
// ---------------------------------------------------------------------------
__device__ __forceinline__ unsigned long long ffma2(unsigned long long a,
                                                    unsigned long long b,
                                                    unsigned long long c) {
    unsigned long long d;
    asm("fma.rn.f32x2 %0, %1, %2, %3;" : "=l"(d) : "l"(a), "l"(b), "l"(c));
    return d;
}
__device__ __forceinline__ unsigned long long dup2(float v) {
    unsigned long long r;
    asm("mov.b64 %0, {%1, %2};" : "=l"(r) : "f"(v), "f"(v));
    return r;
}
__device__ __forceinline__ float2 unpack2(unsigned long long v) {
    float2 r;
    asm("mov.b64 {%0, %1}, %2;" : "=f"(r.x), "=f"(r.y) : "l"(v));
    return r;
}
__device__ __forceinline__ int read_mask(const void* p, int idx, int mode) {
    if (mode == 1) return ((const int*)p)[idx] != 0;
    if (mode == 2) return ((const float*)p)[idx] != 0.0f;
    return ((const unsigned char*)p)[idx] != 0;
}

// ---------------------------------------------------------------------------
// K0: classify mask serialization (u8 / i32 / f32)
// ---------------------------------------------------------------------------
__global__ void its_detect_kernel(const unsigned int* __restrict__ m) {
    __shared__ int not01, not0f;
    if (threadIdx.x == 0) { not01 = 0; not0f = 0; }
    __syncthreads();
    int l01 = 0, l0f = 0;
    for (int i = threadIdx.x; i < QK/4; i += blockDim.x) {
        unsigned v = m[i];
        if (v > 1u) l01 = 1;
        if (v != 0u && v != 0x3F800000u) l0f = 1;
    }
    if (l01) not01 = 1;
    if (l0f) not0f = 1;
    __syncthreads();
    if (threadIdx.x == 0)
        g_mask_mode = (!not01) ? 1 : ((!not0f) ? 2 : 0);
}

// ---------------------------------------------------------------------------
// K1: delta tables: g_demb[dir][d][j] = delta_emb[d] @ w1[128:144, :] + b1[j]
// ---------------------------------------------------------------------------
__global__ void its_tables_kernel(const float* __restrict__ demb,
                                  const float* __restrict__ piw1, const float* __restrict__ pib1,
                                  const float* __restrict__ pow1, const float* __restrict__ pob1) {
    int dir = blockIdx.x;
    const float* w1 = dir ? pow1 : piw1;
    const float* b1 = dir ? pob1 : pib1;
    float* out = g_demb + dir * (65*64);
    for (int idx = threadIdx.x; idx < 65*64; idx += blockDim.x) {
        int d = idx >> 6, j = idx & 63;
        float acc = b1[j];
#pragma unroll
        for (int dd = 0; dd < 16; dd++)
            acc += demb[d*16 + dd] * w1[(128 + dd)*64 + j];
        out[idx] = acc;
    }
}

// ---------------------------------------------------------------------------
// K2: edge aggregation with PER-QUERY EDGE COMPACTION + warp-granular skip.
// One block = one direction x 2 queries (64 edge slots).
// Valid edges compacted to the front of each query's 32-slot window via
// warp ballot; warps whose 8-edge window is entirely past cnt skip the
// GEMM + epilogue (uniform branch). ~50% of GEMM work eliminated.
// ---------------------------------------------------------------------------
__global__ void __launch_bounds__(256, 3)
its_edge_kernel(const float* __restrict__ x,
                const int* __restrict__ in_u,  const int* __restrict__ in_tau,
                const void* __restrict__ in_mask,
                const int* __restrict__ out_u, const int* __restrict__ out_tau,
                const void* __restrict__ out_mask,
                const int* __restrict__ times,
                const float* __restrict__ piw1, const float* __restrict__ pow1) {
    extern __shared__ float sm[];
    float* As    = sm;               // [128 k][68]  (64 edge slots + pad)
    float* Bs    = As + 128*68;      // [128 k][68]  (64 j + pad)
    float* spart = Bs + 128*68;      // [16 groups][64]
    int* sdelta  = (int*)(spart + 16*64);  // [64] compacted
    int* srow    = sdelta + 64;            // [64] compacted
    int* scnt    = srow + 64;              // [2] valid counts per query

    int bid  = blockIdx.x;
    int dir  = (bid >= TILES2) ? 1 : 0;
    int tile = bid - dir * TILES2;
    const int*  uu = dir ? out_u   : in_u;
    const int*  tt = dir ? out_tau : in_tau;
    const void* mm = dir ? out_mask : in_mask;
    const float* w1 = dir ? pow1 : piw1;
    const float* gdemb = g_demb + dir * 4160;
    int tid = threadIdx.x;
    int wid = tid >> 5, lane = tid & 31;
    int mode = g_mask_mode;

    // Stage w1 rows 0..127 (8192 floats)
    for (int i = tid; i < 2048; i += 256) {
        float4 v = ((const float4*)w1)[i];
        int k = i >> 4, j = (i & 15) * 4;
        *(float4*)(Bs + k*68 + j) = v;
    }

    // Metadata + per-query compaction (warp 0 -> query 0, warp 1 -> query 1;
    // lane = original slot within query).
    if (wid < 2) {
        int q = tile*2 + wid;
        int s = tile*TILE_E + wid*32 + lane;
        int t = times[q];
        int u = uu[s], ta = tt[s];
        int d = dir ? (ta - t) : (t - ta);
        d = d < 0 ? 0 : (d > WWIN ? WWIN : d);
        int mk = read_mask(mm, s, mode);
        unsigned bal = __ballot_sync(0xffffffffu, mk);
        int cnt = __popc(bal);
        int pos = __popc(bal & ((1u << lane) - 1u));
        if (mk) {
            sdelta[wid*32 + pos] = d;
            srow[wid*32 + pos]   = u*TT + ta;
        }
        if (lane == 0) {
            scnt[wid] = cnt;
            g_cnt[dir*QQ + q] = cnt;
        }
    }
    __syncthreads();

    int cnt0 = scnt[0], cnt1 = scnt[1];

    // Gather compacted rows -> As transposed [k][e].
    // Zero-fill only up to the last active 8-edge group of each query.
    {
        int e = tid >> 2, h = tid & 3;
        int wq = e >> 5, le = e & 31;
        int cnt = wq ? cnt1 : cnt0;
        int lim = (cnt + 7) & ~7;          // groups beyond lim are skipped warps
        if (le < cnt) {
            const float4* src = (const float4*)(x + (size_t)srow[e]*128) + h*8;
#pragma unroll
            for (int i = 0; i < 8; i++) {
                float4 v = src[i];
                int k0 = h*32 + i*4;
                As[(k0+0)*68 + e] = v.x;
                As[(k0+1)*68 + e] = v.y;
                As[(k0+2)*68 + e] = v.z;
                As[(k0+3)*68 + e] = v.w;
            }
        } else if (le < lim) {
#pragma unroll
            for (int i = 0; i < 8; i++) {
                int k0 = h*32 + i*4;
                As[(k0+0)*68 + e] = 0.0f;
                As[(k0+1)*68 + e] = 0.0f;
                As[(k0+2)*68 + e] = 0.0f;
                As[(k0+3)*68 + e] = 0.0f;
            }
        }
    }
    __syncthreads();

    // Warp w covers edges [8w, 8w+8): warps 0-3 -> query 0, 4-7 -> query 1.
    int r0 = (tid >> 4) * 4;     // global edge base (4 edges)
    int o0 = (tid & 15) * 4;     // j base
    int wq   = wid >> 2;
    int cnt  = wq ? cnt1 : cnt0;
    int ebase = (wid & 3) * 8;   // warp's base edge within its query
    int te = tid >> 4;
    int active = ebase < cnt;

    if (active) {
        unsigned long long acc[2][4];
#pragma unroll
        for (int p = 0; p < 2; p++)
#pragma unroll
            for (int j = 0; j < 4; j++) acc[p][j] = 0ull;

#pragma unroll 8
        for (int k = 0; k < 128; k++) {
            ulonglong2 a = *(const ulonglong2*)(As + k*68 + r0);
            float4 bv = *(const float4*)(Bs + k*68 + o0);
            unsigned long long b0 = dup2(bv.x), b1 = dup2(bv.y);
            unsigned long long b2 = dup2(bv.z), b3 = dup2(bv.w);
            acc[0][0] = ffma2(a.x, b0, acc[0][0]);
            acc[0][1] = ffma2(a.x, b1, acc[0][1]);
            acc[0][2] = ffma2(a.x, b2, acc[0][2]);
            acc[0][3] = ffma2(a.x, b3, acc[0][3]);
            acc[1][0] = ffma2(a.y, b0, acc[1][0]);
            acc[1][1] = ffma2(a.y, b1, acc[1][1]);
            acc[1][2] = ffma2(a.y, b2, acc[1][2]);
            acc[1][3] = ffma2(a.y, b3, acc[1][3]);
        }

        // Epilogue: + demb[delta], relu, sum over this thread's 4 valid edges
        float part[4] = {0.f, 0.f, 0.f, 0.f};
#pragma unroll
        for (int p = 0; p < 2; p++) {
            int e0 = r0 + 2*p, e1 = e0 + 1;
            int v0 = (e0 & 31) < cnt;
            int v1 = (e1 & 31) < cnt;
            float2 c0 = unpack2(acc[p][0]);
            float2 c1 = unpack2(acc[p][1]);
            float2 c2 = unpack2(acc[p][2]);
            float2 c3 = unpack2(acc[p][3]);
            if (v0) {
                float4 dv = *(const float4*)(gdemb + sdelta[e0]*64 + o0);
                part[0] += fmaxf(c0.x + dv.x, 0.f);
                part[1] += fmaxf(c1.x + dv.y, 0.f);
                part[2] += fmaxf(c2.x + dv.z, 0.f);
                part[3] += fmaxf(c3.x + dv.w, 0.f);
            }
            if (v1) {
                float4 dv = *(const float4*)(gdemb + sdelta[e1]*64 + o0);
                part[0] += fmaxf(c0.y + dv.x, 0.f);
                part[1] += fmaxf(c1.y + dv.y, 0.f);
                part[2] += fmaxf(c2.y + dv.z, 0.f);
                part[3] += fmaxf(c3.y + dv.w, 0.f);
            }
        }
        spart[te*64 + o0 + 0] = part[0];
        spart[te*64 + o0 + 1] = part[1];
        spart[te*64 + o0 + 2] = part[2];
        spart[te*64 + o0 + 3] = part[3];
    } else {
        // Inactive warp: contribute zeros to the deterministic reduce.
        spart[te*64 + o0 + 0] = 0.f;
        spart[te*64 + o0 + 1] = 0.f;
        spart[te*64 + o0 + 2] = 0.f;
        spart[te*64 + o0 + 3] = 0.f;
    }
    __syncthreads();

    // Deterministic reduce: 8 groups per query
    if (tid < 128) {
        int q = tid >> 6, j = tid & 63;
        float s = 0.f;
#pragma unroll
        for (int g = 0; g < 8; g++) s += spart[(q*8 + g)*64 + j];
        g_hsum[(size_t)dir*QQ*64 + (size_t)(tile*2 + q)*64 + j] = s;
    }
}

// ---------------------------------------------------------------------------
// K3: per-query m_in/m_out (hsum @ w2 / cnt + b2) + x_vt gather -> g_feat[Q,256]
// ---------------------------------------------------------------------------
#define QT 24
__global__ void __launch_bounds__(256)
its_combine_a_kernel(const float* __restrict__ x,
                     const int* __restrict__ node_ids, const int* __restrict__ times,
                     const float* __restrict__ piw2, const float* __restrict__ pib2,
                     const float* __restrict__ pow2, const float* __restrict__ pob2) {
    __shared__ float s_w2[2*64*64];
    __shared__ float s_hs[2*QT*64];
    __shared__ float s_b2[2*64];
    __shared__ int   s_cnt[2*QT];

    int qb = blockIdx.x * QT;
    int tid = threadIdx.x;

    for (int i = tid; i < 4096; i += 256) {
        s_w2[i]        = piw2[i];
        s_w2[4096 + i] = pow2[i];
    }
    if (tid < 64) { s_b2[tid] = pib2[tid]; s_b2[64 + tid] = pob2[tid]; }
    for (int i = tid; i < QT*64; i += 256) {
        int qi = i >> 6, j = i & 63;
        s_hs[i]         = g_hsum[(size_t)(qb + qi)*64 + j];
        s_hs[QT*64 + i] = g_hsum[(size_t)QQ*64 + (size_t)(qb + qi)*64 + j];
    }
    if (tid < 2*QT) {
        int dir = tid >= QT, qi = tid - dir*QT;
        s_cnt[tid] = g_cnt[dir*QQ + qb + qi];
    }
    __syncthreads();

    for (int task = tid; task < 2*QT*8; task += 256) {
        int r = task >> 3, c = task & 7;
        int dir = r >= QT, qi = r - dir*QT;
        const float* hs = s_hs + dir*QT*64 + qi*64;
        const float* w2 = s_w2 + dir*4096;
        float acc[8] = {0,0,0,0,0,0,0,0};
#pragma unroll 8
        for (int k = 0; k < 64; k++) {
            float h = hs[k];
            const float* wr = w2 + k*64 + c*8;
            float4 w0 = *(const float4*)wr;
            float4 w1 = *(const float4*)(wr + 4);
            acc[0] += h*w0.x; acc[1] += h*w0.y; acc[2] += h*w0.z; acc[3] += h*w0.w;
            acc[4] += h*w1.x; acc[5] += h*w1.y; acc[6] += h*w1.z; acc[7] += h*w1.w;
        }
        int cnt = s_cnt[dir*QT + qi];
        float inv = 1.0f / (float)(cnt > 1 ? cnt : 1);
        float bsc = cnt > 0 ? 1.0f : 0.0f;
        float* dst = g_feat + (size_t)(qb + qi)*256 + 128 + dir*64 + c*8;
#pragma unroll
        for (int j = 0; j < 8; j++)
            dst[j] = acc[j]*inv + bsc * s_b2[dir*64 + c*8 + j];
    }

    for (int task = tid; task < QT*16; task += 256) {
        int qi = task >> 4, part = task & 15;
        int q = qb + qi;
        const float* src = x + (size_t)node_ids[q]*8192 + (size_t)times[q]*128 + part*8;
        float* dst = g_feat + (size_t)q*256 + part*8;
        float4 a = ((const float4*)src)[0];
        float4 b = ((const float4*)src)[1];
        ((float4*)dst)[0] = a;
        ((float4*)dst)[1] = b;
    }
}

// ---------------------------------------------------------------------------
// K4: u1 = relu(feat @ cw1 + cb1)   [Q,256]@[256,128]
// ---------------------------------------------------------------------------
__global__ void __launch_bounds__(256)
its_gemm1_kernel(const float* __restrict__ cw1, const float* __restrict__ cb1) {
    __shared__ float As[32*68];
    __shared__ float Bs[32*128];
    int qb = blockIdx.x * 64;
    int tid = threadIdx.x;
    int qg = (tid >> 4) * 4;
    int j0 = (tid & 15) * 8;

    unsigned long long acc[4][4];
#pragma unroll
    for (int a = 0; a < 4; a++)
#pragma unroll
        for (int b = 0; b < 4; b++) acc[a][b] = 0ull;

    for (int kc = 0; kc < 256; kc += 32) {
        {
            int q = tid >> 2, kq = tid & 3;
            const float* src = g_feat + (size_t)(qb + q)*256 + kc + kq*8;
            float4 v0 = ((const float4*)src)[0];
            float4 v1 = ((const float4*)src)[1];
            int k0 = kq*8;
            As[(k0+0)*68 + q] = v0.x; As[(k0+1)*68 + q] = v0.y;
            As[(k0+2)*68 + q] = v0.z; As[(k0+3)*68 + q] = v0.w;
            As[(k0+4)*68 + q] = v1.x; As[(k0+5)*68 + q] = v1.y;
            As[(k0+6)*68 + q] = v1.z; As[(k0+7)*68 + q] = v1.w;
        }
        {
            int k = tid >> 3, jb = (tid & 7) * 16;
            const float4* src = (const float4*)(cw1 + (size_t)(kc + k)*128 + jb);
            float4* dst = (float4*)(Bs + k*128 + jb);
            dst[0] = src[0]; dst[1] = src[1]; dst[2] = src[2]; dst[3] = src[3];
        }
        __syncthreads();
#pragma unroll
        for (int k = 0; k < 32; k++) {
            float4 av = *(const float4*)(As + k*68 + qg);
            ulonglong2 bA = *(const ulonglong2*)(Bs + k*128 + j0);
            ulonglong2 bB = *(const ulonglong2*)(Bs + k*128 + j0 + 4);
            unsigned long long a0 = dup2(av.x), a1 = dup2(av.y);
            unsigned long long a2 = dup2(av.z), a3 = dup2(av.w);
            acc[0][0] = ffma2(a0, bA.x, acc[0][0]); acc[0][1] = ffma2(a0, bA.y, acc[0][1]);
            acc[0][2] = ffma2(a0, bB.x, acc[0][2]); acc[0][3] = ffma2(a0, bB.y, acc[0][3]);
            acc[1][0] = ffma2(a1, bA.x, acc[1][0]); acc[1][1] = ffma2(a1, bA.y, acc[1][1]);
            acc[1][2] = ffma2(a1, bB.x, acc[1][2]); acc[1][3] = ffma2(a1, bB.y, acc[1][3]);
            acc[2][0] = ffma2(a2, bA.x, acc[2][0]); acc[2][1] = ffma2(a2, bA.y, acc[2][1]);
            acc[2][2] = ffma2(a2, bB.x, acc[2][2]); acc[2][3] = ffma2(a2, bB.y, acc[2][3]);
            acc[3][0] = ffma2(a3, bA.x, acc[3][0]); acc[3][1] = ffma2(a3, bA.y, acc[3][1]);
            acc[3][2] = ffma2(a3, bB.x, acc[3][2]); acc[3][3] = ffma2(a3, bB.y, acc[3][3]);
        }
        __syncthreads();
    }

#pragma unroll
    for (int jp = 0; jp < 4; jp++) {
        int j = j0 + jp*2;
        float b0 = cb1[j], b1 = cb1[j+1];
#pragma unroll
        for (int qi = 0; qi < 4; qi++) {
            float2 v = unpack2(acc[qi][jp]);
            float r0 = v.x + b0; r0 = r0 > 0.f ? r0 : 0.f;
            float r1 = v.y + b1; r1 = r1 > 0.f ? r1 : 0.f;
            float* dst = g_u1 + (size_t)(qb + qg + qi)*128 + j;
            dst[0] = r0; dst[1] = r1;
        }
    }
}

// ---------------------------------------------------------------------------
// K5: h = relu(u1 @ cw2 + cb2)  [Q,128]@[128,64] -> scatter into g_feat2
// ---------------------------------------------------------------------------
__global__ void __launch_bounds__(256)
its_gemm2_kernel(const float* __restrict__ cw2, const float* __restrict__ cb2) {
    __shared__ float As[32*68];
    __shared__ float Bs[32*64];
    int qb = blockIdx.x * 64;
    int tid = threadIdx.x;
    int qg = (tid >> 4) * 4;
    int j0 = (tid & 15) * 4;

    float acc[4][4];
#pragma unroll
    for (int a = 0; a < 4; a++)
#pragma unroll
        for (int b = 0; b < 4; b++) acc[a][b] = 0.f;

    for (int kc = 0; kc < 128; kc += 32) {
        {
            int q = tid >> 2, kq = tid & 3;
            const float* src = g_u1 + (size_t)(qb + q)*128 + kc + kq*8;
            float4 v0 = ((const float4*)src)[0];
            float4 v1 = ((const float4*)src)[1];
            int k0 = kq*8;
            As[(k0+0)*68 + q] = v0.x; As[(k0+1)*68 + q] = v0.y;
            As[(k0+2)*68 + q] = v0.z; As[(k0+3)*68 + q] = v0.w;
            As[(k0+4)*68 + q] = v1.x; As[(k0+5)*68 + q] = v1.y;
            As[(k0+6)*68 + q] = v1.z; As[(k0+7)*68 + q] = v1.w;
        }
        {
            int k = tid >> 3, jb = (tid & 7) * 8;
            const float4* src = (const float4*)(cw2 + (size_t)(kc + k)*64 + jb);
            float4* dst = (float4*)(Bs + k*64 + jb);
            dst[0] = src[0]; dst[1] = src[1];
        }
        __syncthreads();
#pragma unroll
        for (int k = 0; k < 32; k++) {
            float4 av = *(const float4*)(As + k*68 + qg);
            float4 bv = *(const float4*)(Bs + k*64 + j0);
            acc[0][0] += av.x*bv.x; acc[0][1] += av.x*bv.y; acc[0][2] += av.x*bv.z; acc[0][3] += av.x*bv.w;
            acc[1][0] += av.y*bv.x; acc[1][1] += av.y*bv.y; acc[1][2] += av.y*bv.z; acc[1][3] += av.y*bv.w;
            acc[2][0] += av.z*bv.x; acc[2][1] += av.z*bv.y; acc[2][2] += av.z*bv.z; acc[2][3] += av.z*bv.w;
            acc[3][0] += av.w*bv.x; acc[3][1] += av.w*bv.y; acc[3][2] += av.w*bv.z; acc[3][3] += av.w*bv.w;
        }
        __syncthreads();
    }

#pragma unroll
    for (int qi = 0; qi < 4; qi++) {
        int gq = qb + qg + qi;
        int bb = gq / 3;
        int slot = gq - bb*3;
        float* dst = g_feat2 + (size_t)bb*193 + slot*64 + j0;
#pragma unroll
        for (int j = 0; j < 4; j++) {
            float h = acc[qi][j] + cb2[j0 + j];
            dst[j] = h > 0.f ? h : 0.f;
        }
    }
}

// ---------------------------------------------------------------------------
// K6: out[b] = relu(feat2 @ sw1 + sb1) @ sw2 + sb2
// Block = 32 b; sw1 (99KB) staged ONCE per block in dynamic smem.
// ---------------------------------------------------------------------------
__global__ void __launch_bounds__(256)
its_score_kernel(const float* __restrict__ sw1, const float* __restrict__ sb1,
                 const float* __restrict__ sw2, const float* __restrict__ sb2,
                 const float* __restrict__ d_norm, float* __restrict__ out) {
    extern __shared__ float smsc[];
    float* s_w1 = smsc;              // [193*128]
    float* srow = smsc + 24704;      // [8][200]
    int tid = threadIdx.x;
    int w = tid >> 5, lane = tid & 31;

    for (int i = tid; i < 6176; i += 256)
        ((float4*)s_w1)[i] = ((const float4*)sw1)[i];
    __syncthreads();

    float4 w2v = *(const float4*)(sw2 + lane*4);
    float sbias = sb2[0];
    float b1v0 = sb1[lane*4+0], b1v1 = sb1[lane*4+1];
    float b1v2 = sb1[lane*4+2], b1v3 = sb1[lane*4+3];

#pragma unroll
    for (int sub = 0; sub < 4; sub++) {
        int b = blockIdx.x * 32 + w * 4 + sub;
        for (int k = lane; k < 192; k += 32)
            srow[w*200 + k] = g_feat2[(size_t)b*193 + k];
        if (lane == 0) srow[w*200 + 192] = d_norm[b];
        __syncwarp();

        float a0 = 0.f, a1 = 0.f, a2 = 0.f, a3 = 0.f;
        for (int k = 0; k < 193; k++) {
            float f = srow[w*200 + k];
            float4 wv = *(const float4*)(s_w1 + k*128 + lane*4);
            a0 += f*wv.x; a1 += f*wv.y; a2 += f*wv.z; a3 += f*wv.w;
        }
        float v0 = fmaxf(a0 + b1v0, 0.f);
        float v1 = fmaxf(a1 + b1v1, 0.f);
        float v2 = fmaxf(a2 + b1v2, 0.f);
        float v3 = fmaxf(a3 + b1v3, 0.f);
        float p = v0*w2v.x + v1*w2v.y + v2*w2v.z + v3*w2v.w;
#pragma unroll
        for (int off = 16; off > 0; off >>= 1)
            p += __shfl_xor_sync(0xffffffffu, p, off);
        if (lane == 0) out[b] = p + sbias;
        __syncwarp();
    }
}

// ---------------------------------------------------------------------------
// kernel_launch
// ---------------------------------------------------------------------------
extern "C" void kernel_launch(void* const* d_in, const int* in_sizes, int n_in,
                              void* d_out, int out_size) {
    const float* x       = (const float*)d_in[0];
    const float* d_norm  = (const float*)d_in[1];
    const float* demb    = (const float*)d_in[2];
    const float* piw1    = (const float*)d_in[3];
    const float* pib1    = (const float*)d_in[4];
    const float* piw2    = (const float*)d_in[5];
    const float* pib2    = (const float*)d_in[6];
    const float* pow1    = (const float*)d_in[7];
    const float* pob1    = (const float*)d_in[8];
    const float* pow2    = (const float*)d_in[9];
    const float* pob2    = (const float*)d_in[10];
    const float* cw1     = (const float*)d_in[11];
    const float* cb1     = (const float*)d_in[12];
    const float* cw2     = (const float*)d_in[13];
    const float* cb2     = (const float*)d_in[14];
    const float* sw1     = (const float*)d_in[15];
    const float* sb1     = (const float*)d_in[16];
    const float* sw2     = (const float*)d_in[17];
    const float* sb2     = (const float*)d_in[18];
    const int* node_ids  = (const int*)d_in[19];
    const int* times     = (const int*)d_in[20];
    const int* in_u      = (const int*)d_in[21];
    const int* in_tau    = (const int*)d_in[22];
    const void* in_mask  = d_in[23];
    const int* out_u     = (const int*)d_in[24];
    const int* out_tau   = (const int*)d_in[25];
    const void* out_mask = d_in[26];
    float* out = (float*)d_out;

    cudaFuncSetAttribute(its_edge_kernel,
                         cudaFuncAttributeMaxDynamicSharedMemorySize, SMEM_EK);
    cudaFuncSetAttribute(its_score_kernel,
                         cudaFuncAttributeMaxDynamicSharedMemorySize, SMEM_SC);

    its_detect_kernel<<<1, 256>>>((const unsigned int*)in_mask);
    its_tables_kernel<<<2, 256>>>(demb, piw1, pib1, pow1, pob1);
    its_edge_kernel<<<2*TILES2, 256, SMEM_EK>>>(x,
        in_u, in_tau, in_mask, out_u, out_tau, out_mask, times, piw1, pow1);
    its_combine_a_kernel<<<QQ/QT, 256>>>(x, node_ids, times, piw2, pib2, pow2, pob2);
    its_gemm1_kernel<<<QQ/64, 256>>>(cw1, cb1);
    its_gemm2_kernel<<<QQ/64, 256>>>(cw2, cb2);
    its_score_kernel<<<BB/32, 256, SMEM_SC>>>(sw1, sb1, sw2, sb2, d_norm, out);
}

// round 14
// speedup vs baseline: 1.7321x; 1.0318x over previous
#include <cuda_runtime.h>
#include <cuda_bf16.h>
#include <cstdint>

// ---------------------------------------------------------------------------
// Problem constants
// ---------------------------------------------------------------------------
#define NN      20000
#define TT      64
#define FF      128
#define BB      8192
#define KK      32
#define QQ      (3*BB)            // 24576
#define WWIN    64
#define QK      (QQ*KK)           // 786432
#define TILE_E  64                // edges per tile (= 2 full queries)
#define TILES2  (QK/TILE_E)       // 12288 tiles per direction
#define NTILE   8                 // tiles per block (w1 staged once)
#define EBLK    (TILES2/NTILE)    // 1536 blocks per direction

// Edge-kernel dynamic smem (floats): As[128][68] | Bs[128][68] | spart[16][64] | meta(192)
#define SMEM_EK ((128*68 + 128*68 + 16*64 + 192) * 4)   // 74496 B -> occupancy 3

// Score-kernel dynamic smem (floats): s_w1[193*128] | srow[8][200]
#define SMEM_SC ((193*128 + 8*200) * 4)                 // 105216 B

// ---------------------------------------------------------------------------
// Device scratch (static __device__ arrays — allocation APIs are forbidden)
// ---------------------------------------------------------------------------
__device__ int    g_mask_mode;                // 0=u8, 1=i32, 2=f32
__device__ float  g_demb[2*65*64];            // per-dir (delta_emb@w1_delta + b1)
__device__ float  g_hsum[2*(size_t)QQ*64];    // per-(dir,query) sum of relu hidden
__device__ int    g_cnt[2*QQ];                // per-(dir,query) valid-edge count
__device__ float  g_feat[(size_t)QQ*256];     // [x_vt | m_in | m_out]
__device__ float  g_u1[(size_t)QQ*128];       // combine hidden 1
__device__ float  g_feat2[(size_t)BB*193];    // scorer features

// ---------------------------------------------------------------------------
// f32x2 helpers (sm_103a packed fp32 — 2x FFMA throughput)
// ---------------------------------------------------------------------------
__device__ __forceinline__ unsigned long long ffma2(unsigned long long a,
                                                    unsigned long long b,
                                                    unsigned long long c) {
    unsigned long long d;
    asm("fma.rn.f32x2 %0, %1, %2, %3;" : "=l"(d) : "l"(a), "l"(b), "l"(c));
    return d;
}
__device__ __forceinline__ unsigned long long dup2(float v) {
    unsigned long long r;
    asm("mov.b64 %0, {%1, %2};" : "=l"(r) : "f"(v), "f"(v));
    return r;
}
__device__ __forceinline__ float2 unpack2(unsigned long long v) {
    float2 r;
    asm("mov.b64 {%0, %1}, %2;" : "=f"(r.x), "=f"(r.y) : "l"(v));
    return r;
}
__device__ __forceinline__ int read_mask(const void* p, int idx, int mode) {
    if (mode == 1) return ((const int*)p)[idx] != 0;
    if (mode == 2) return ((const float*)p)[idx] != 0.0f;
    return ((const unsigned char*)p)[idx] != 0;
}

// ---------------------------------------------------------------------------
// K0: classify mask serialization (u8 / i32 / f32)
// ---------------------------------------------------------------------------
__global__ void its_detect_kernel(const unsigned int* __restrict__ m) {
    __shared__ int not01, not0f;
    if (threadIdx.x == 0) { not01 = 0; not0f = 0; }
    __syncthreads();
    int l01 = 0, l0f = 0;
    for (int i = threadIdx.x; i < QK/4; i += blockDim.x) {
        unsigned v = m[i];
        if (v > 1u) l01 = 1;
        if (v != 0u && v != 0x3F800000u) l0f = 1;
    }
    if (l01) not01 = 1;
    if (l0f) not0f = 1;
    __syncthreads();
    if (threadIdx.x == 0)
        g_mask_mode = (!not01) ? 1 : ((!not0f) ? 2 : 0);
}

// ---------------------------------------------------------------------------
// K1: delta tables: g_demb[dir][d][j] = delta_emb[d] @ w1[128:144, :] + b1[j]
// ---------------------------------------------------------------------------
__global__ void its_tables_kernel(const float* __restrict__ demb,
                                  const float* __restrict__ piw1, const float* __restrict__ pib1,
                                  const float* __restrict__ pow1, const float* __restrict__ pob1) {
    int dir = blockIdx.x;
    const float* w1 = dir ? pow1 : piw1;
    const float* b1 = dir ? pob1 : pib1;
    float* out = g_demb + dir * (65*64);
    for (int idx = threadIdx.x; idx < 65*64; idx += blockDim.x) {
        int d = idx >> 6, j = idx & 63;
        float acc = b1[j];
#pragma unroll
        for (int dd = 0; dd < 16; dd++)
            acc += demb[d*16 + dd] * w1[(128 + dd)*64 + j];
        out[idx] = acc;
    }
}

// ---------------------------------------------------------------------------
// K2: edge aggregation, compaction + warp skip + MULTI-TILE w1 amortization.
// Block = 1 dir x NTILE tiles (16 queries). w1 staged into smem ONCE per
// block (8x less staging traffic than one-tile blocks). Per tile: per-query
// edge compaction via ballot, mask-skipped gather, FFMA2 GEMM with
// warp-granular skip, demb[delta]+relu epilogue, deterministic reduce.
// ---------------------------------------------------------------------------
__global__ void __launch_bounds__(256, 3)
its_edge_kernel(const float* __restrict__ x,
                const int* __restrict__ in_u,  const int* __restrict__ in_tau,
                const void* __restrict__ in_mask,
                const int* __restrict__ out_u, const int* __restrict__ out_tau,
                const void* __restrict__ out_mask,
                const int* __restrict__ times,
                const float* __restrict__ piw1, const float* __restrict__ pow1) {
    extern __shared__ float sm[];
    float* As    = sm;               // [128 k][68]  (64 edge slots + pad)
    float* Bs    = As + 128*68;      // [128 k][68]  (64 j + pad)
    float* spart = Bs + 128*68;      // [16 groups][64]
    int* sdelta  = (int*)(spart + 16*64);  // [64] compacted
    int* srow    = sdelta + 64;            // [64] compacted
    int* scnt    = srow + 64;              // [2] valid counts per query

    int bid  = blockIdx.x;
    int dir  = (bid >= EBLK) ? 1 : 0;
    int bslot = bid - dir * EBLK;
    const int*  uu = dir ? out_u   : in_u;
    const int*  tt = dir ? out_tau : in_tau;
    const void* mm = dir ? out_mask : in_mask;
    const float* w1 = dir ? pow1 : piw1;
    const float* gdemb = g_demb + dir * 4160;
    int tid = threadIdx.x;
    int wid = tid >> 5, lane = tid & 31;
    int mode = g_mask_mode;

    // Stage w1 rows 0..127 ONCE per block (8192 floats)
    for (int i = tid; i < 2048; i += 256) {
        float4 v = ((const float4*)w1)[i];
        int k = i >> 4, j = (i & 15) * 4;
        *(float4*)(Bs + k*68 + j) = v;
    }

    // Thread-invariant GEMM coordinates
    int r0 = (tid >> 4) * 4;     // edge base (4 edges)
    int o0 = (tid & 15) * 4;     // j base
    int wq = wid >> 2;           // warp's query (0/1)
    int ebase = (wid & 3) * 8;   // warp's base edge within its query
    int te = tid >> 4;

    for (int it = 0; it < NTILE; it++) {
        int tile = bslot * NTILE + it;

        // Metadata + per-query compaction (warp 0 -> q0, warp 1 -> q1)
        if (wid < 2) {
            int q = tile*2 + wid;
            int s = tile*TILE_E + wid*32 + lane;
            int t = times[q];
            int u = uu[s], ta = tt[s];
            int d = dir ? (ta - t) : (t - ta);
            d = d < 0 ? 0 : (d > WWIN ? WWIN : d);
            int mk = read_mask(mm, s, mode);
            unsigned bal = __ballot_sync(0xffffffffu, mk);
            int cnt = __popc(bal);
            int pos = __popc(bal & ((1u << lane) - 1u));
            if (mk) {
                sdelta[wid*32 + pos] = d;
                srow[wid*32 + pos]   = u*TT + ta;
            }
            if (lane == 0) {
                scnt[wid] = cnt;
                g_cnt[dir*QQ + q] = cnt;
            }
        }
        __syncthreads();

        int cnt0 = scnt[0], cnt1 = scnt[1];

        // Gather compacted rows -> As transposed [k][e]
        {
            int e = tid >> 2, h = tid & 3;
            int ewq = e >> 5, le = e & 31;
            int cnt = ewq ? cnt1 : cnt0;
            int lim = (cnt + 7) & ~7;
            if (le < cnt) {
                const float4* src = (const float4*)(x + (size_t)srow[e]*128) + h*8;
#pragma unroll
                for (int i = 0; i < 8; i++) {
                    float4 v = src[i];
                    int k0 = h*32 + i*4;
                    As[(k0+0)*68 + e] = v.x;
                    As[(k0+1)*68 + e] = v.y;
                    As[(k0+2)*68 + e] = v.z;
                    As[(k0+3)*68 + e] = v.w;
                }
            } else if (le < lim) {
#pragma unroll
                for (int i = 0; i < 8; i++) {
                    int k0 = h*32 + i*4;
                    As[(k0+0)*68 + e] = 0.0f;
                    As[(k0+1)*68 + e] = 0.0f;
                    As[(k0+2)*68 + e] = 0.0f;
                    As[(k0+3)*68 + e] = 0.0f;
                }
            }
        }
        __syncthreads();

        int cnt = wq ? cnt1 : cnt0;
        int active = ebase < cnt;

        if (active) {
            unsigned long long acc[2][4];
#pragma unroll
            for (int p = 0; p < 2; p++)
#pragma unroll
                for (int j = 0; j < 4; j++) acc[p][j] = 0ull;

#pragma unroll 8
            for (int k = 0; k < 128; k++) {
                ulonglong2 a = *(const ulonglong2*)(As + k*68 + r0);
                float4 bv = *(const float4*)(Bs + k*68 + o0);
                unsigned long long b0 = dup2(bv.x), b1 = dup2(bv.y);
                unsigned long long b2 = dup2(bv.z), b3 = dup2(bv.w);
                acc[0][0] = ffma2(a.x, b0, acc[0][0]);
                acc[0][1] = ffma2(a.x, b1, acc[0][1]);
                acc[0][2] = ffma2(a.x, b2, acc[0][2]);
                acc[0][3] = ffma2(a.x, b3, acc[0][3]);
                acc[1][0] = ffma2(a.y, b0, acc[1][0]);
                acc[1][1] = ffma2(a.y, b1, acc[1][1]);
                acc[1][2] = ffma2(a.y, b2, acc[1][2]);
                acc[1][3] = ffma2(a.y, b3, acc[1][3]);
            }

            float part[4] = {0.f, 0.f, 0.f, 0.f};
#pragma unroll
            for (int p = 0; p < 2; p++) {
                int e0 = r0 + 2*p, e1 = e0 + 1;
                int v0 = (e0 & 31) < cnt;
                int v1 = (e1 & 31) < cnt;
                float2 c0 = unpack2(acc[p][0]);
                float2 c1 = unpack2(acc[p][1]);
                float2 c2 = unpack2(acc[p][2]);
                float2 c3 = unpack2(acc[p][3]);
                if (v0) {
                    float4 dv = *(const float4*)(gdemb + sdelta[e0]*64 + o0);
                    part[0] += fmaxf(c0.x + dv.x, 0.f);
                    part[1] += fmaxf(c1.x + dv.y, 0.f);
                    part[2] += fmaxf(c2.x + dv.z, 0.f);
                    part[3] += fmaxf(c3.x + dv.w, 0.f);
                }
                if (v1) {
                    float4 dv = *(const float4*)(gdemb + sdelta[e1]*64 + o0);
                    part[0] += fmaxf(c0.y + dv.x, 0.f);
                    part[1] += fmaxf(c1.y + dv.y, 0.f);
                    part[2] += fmaxf(c2.y + dv.z, 0.f);
                    part[3] += fmaxf(c3.y + dv.w, 0.f);
                }
            }
            spart[te*64 + o0 + 0] = part[0];
            spart[te*64 + o0 + 1] = part[1];
            spart[te*64 + o0 + 2] = part[2];
            spart[te*64 + o0 + 3] = part[3];
        } else {
            spart[te*64 + o0 + 0] = 0.f;
            spart[te*64 + o0 + 1] = 0.f;
            spart[te*64 + o0 + 2] = 0.f;
            spart[te*64 + o0 + 3] = 0.f;
        }
        __syncthreads();

        // Deterministic reduce: 8 groups per query
        if (tid < 128) {
            int q = tid >> 6, j = tid & 63;
            float s = 0.f;
#pragma unroll
            for (int g = 0; g < 8; g++) s += spart[(q*8 + g)*64 + j];
            g_hsum[(size_t)dir*QQ*64 + (size_t)(tile*2 + q)*64 + j] = s;
        }
        __syncthreads();   // metadata/As safe to overwrite next iteration
    }
}

// ---------------------------------------------------------------------------
// K3: per-query m_in/m_out (hsum @ w2 / cnt + b2) + x_vt gather -> g_feat[Q,256]
// ---------------------------------------------------------------------------
#define QT 24
__global__ void __launch_bounds__(256)
its_combine_a_kernel(const float* __restrict__ x,
                     const int* __restrict__ node_ids, const int* __restrict__ times,
                     const float* __restrict__ piw2, const float* __restrict__ pib2,
                     const float* __restrict__ pow2, const float* __restrict__ pob2) {
    __shared__ float s_w2[2*64*64];
    __shared__ float s_hs[2*QT*64];
    __shared__ float s_b2[2*64];
    __shared__ int   s_cnt[2*QT];

    int qb = blockIdx.x * QT;
    int tid = threadIdx.x;

    for (int i = tid; i < 4096; i += 256) {
        s_w2[i]        = piw2[i];
        s_w2[4096 + i] = pow2[i];
    }
    if (tid < 64) { s_b2[tid] = pib2[tid]; s_b2[64 + tid] = pob2[tid]; }
    for (int i = tid; i < QT*64; i += 256) {
        int qi = i >> 6, j = i & 63;
        s_hs[i]         = g_hsum[(size_t)(qb + qi)*64 + j];
        s_hs[QT*64 + i] = g_hsum[(size_t)QQ*64 + (size_t)(qb + qi)*64 + j];
    }
    if (tid < 2*QT) {
        int dir = tid >= QT, qi = tid - dir*QT;
        s_cnt[tid] = g_cnt[dir*QQ + qb + qi];
    }
    __syncthreads();

    for (int task = tid; task < 2*QT*8; task += 256) {
        int r = task >> 3, c = task & 7;
        int dir = r >= QT, qi = r - dir*QT;
        const float* hs = s_hs + dir*QT*64 + qi*64;
        const float* w2 = s_w2 + dir*4096;
        float acc[8] = {0,0,0,0,0,0,0,0};
#pragma unroll 8
        for (int k = 0; k < 64; k++) {
            float h = hs[k];
            const float* wr = w2 + k*64 + c*8;
            float4 w0 = *(const float4*)wr;
            float4 w1 = *(const float4*)(wr + 4);
            acc[0] += h*w0.x; acc[1] += h*w0.y; acc[2] += h*w0.z; acc[3] += h*w0.w;
            acc[4] += h*w1.x; acc[5] += h*w1.y; acc[6] += h*w1.z; acc[7] += h*w1.w;
        }
        int cnt = s_cnt[dir*QT + qi];
        float inv = 1.0f / (float)(cnt > 1 ? cnt : 1);
        float bsc = cnt > 0 ? 1.0f : 0.0f;
        float* dst = g_feat + (size_t)(qb + qi)*256 + 128 + dir*64 + c*8;
#pragma unroll
        for (int j = 0; j < 8; j++)
            dst[j] = acc[j]*inv + bsc * s_b2[dir*64 + c*8 + j];
    }

    for (int task = tid; task < QT*16; task += 256) {
        int qi = task >> 4, part = task & 15;
        int q = qb + qi;
        const float* src = x + (size_t)node_ids[q]*8192 + (size_t)times[q]*128 + part*8;
        float* dst = g_feat + (size_t)q*256 + part*8;
        float4 a = ((const float4*)src)[0];
        float4 b = ((const float4*)src)[1];
        ((float4*)dst)[0] = a;
        ((float4*)dst)[1] = b;
    }
}

// ---------------------------------------------------------------------------
// K4: u1 = relu(feat @ cw1 + cb1)   [Q,256]@[256,128]
// ---------------------------------------------------------------------------
__global__ void __launch_bounds__(256)
its_gemm1_kernel(const float* __restrict__ cw1, const float* __restrict__ cb1) {
    __shared__ float As[32*68];
    __shared__ float Bs[32*128];
    int qb = blockIdx.x * 64;
    int tid = threadIdx.x;
    int qg = (tid >> 4) * 4;
    int j0 = (tid & 15) * 8;

    unsigned long long acc[4][4];
#pragma unroll
    for (int a = 0; a < 4; a++)
#pragma unroll
        for (int b = 0; b < 4; b++) acc[a][b] = 0ull;

    for (int kc = 0; kc < 256; kc += 32) {
        {
            int q = tid >> 2, kq = tid & 3;
            const float* src = g_feat + (size_t)(qb + q)*256 + kc + kq*8;
            float4 v0 = ((const float4*)src)[0];
            float4 v1 = ((const float4*)src)[1];
            int k0 = kq*8;
            As[(k0+0)*68 + q] = v0.x; As[(k0+1)*68 + q] = v0.y;
            As[(k0+2)*68 + q] = v0.z; As[(k0+3)*68 + q] = v0.w;
            As[(k0+4)*68 + q] = v1.x; As[(k0+5)*68 + q] = v1.y;
            As[(k0+6)*68 + q] = v1.z; As[(k0+7)*68 + q] = v1.w;
        }
        {
            int k = tid >> 3, jb = (tid & 7) * 16;
            const float4* src = (const float4*)(cw1 + (size_t)(kc + k)*128 + jb);
            float4* dst = (float4*)(Bs + k*128 + jb);
            dst[0] = src[0]; dst[1] = src[1]; dst[2] = src[2]; dst[3] = src[3];
        }
        __syncthreads();
#pragma unroll
        for (int k = 0; k < 32; k++) {
            float4 av = *(const float4*)(As + k*68 + qg);
            ulonglong2 bA = *(const ulonglong2*)(Bs + k*128 + j0);
            ulonglong2 bB = *(const ulonglong2*)(Bs + k*128 + j0 + 4);
            unsigned long long a0 = dup2(av.x), a1 = dup2(av.y);
            unsigned long long a2 = dup2(av.z), a3 = dup2(av.w);
            acc[0][0] = ffma2(a0, bA.x, acc[0][0]); acc[0][1] = ffma2(a0, bA.y, acc[0][1]);
            acc[0][2] = ffma2(a0, bB.x, acc[0][2]); acc[0][3] = ffma2(a0, bB.y, acc[0][3]);
            acc[1][0] = ffma2(a1, bA.x, acc[1][0]); acc[1][1] = ffma2(a1, bA.y, acc[1][1]);
            acc[1][2] = ffma2(a1, bB.x, acc[1][2]); acc[1][3] = ffma2(a1, bB.y, acc[1][3]);
            acc[2][0] = ffma2(a2, bA.x, acc[2][0]); acc[2][1] = ffma2(a2, bA.y, acc[2][1]);
            acc[2][2] = ffma2(a2, bB.x, acc[2][2]); acc[2][3] = ffma2(a2, bB.y, acc[2][3]);
            acc[3][0] = ffma2(a3, bA.x, acc[3][0]); acc[3][1] = ffma2(a3, bA.y, acc[3][1]);
            acc[3][2] = ffma2(a3, bB.x, acc[3][2]); acc[3][3] = ffma2(a3, bB.y, acc[3][3]);
        }
        __syncthreads();
    }

#pragma unroll
    for (int jp = 0; jp < 4; jp++) {
        int j = j0 + jp*2;
        float b0 = cb1[j], b1 = cb1[j+1];
#pragma unroll
        for (int qi = 0; qi < 4; qi++) {
            float2 v = unpack2(acc[qi][jp]);
            float r0 = v.x + b0; r0 = r0 > 0.f ? r0 : 0.f;
            float r1 = v.y + b1; r1 = r1 > 0.f ? r1 : 0.f;
            float* dst = g_u1 + (size_t)(qb + qg + qi)*128 + j;
            dst[0] = r0; dst[1] = r1;
        }
    }
}

// ---------------------------------------------------------------------------
// K5: h = relu(u1 @ cw2 + cb2)  [Q,128]@[128,64] -> scatter into g_feat2
// ---------------------------------------------------------------------------
__global__ void __launch_bounds__(256)
its_gemm2_kernel(const float* __restrict__ cw2, const float* __restrict__ cb2) {
    __shared__ float As[32*68];
    __shared__ float Bs[32*64];
    int qb = blockIdx.x * 64;
    int tid = threadIdx.x;
    int qg = (tid >> 4) * 4;
    int j0 = (tid & 15) * 4;

    float acc[4][4];
#pragma unroll
    for (int a = 0; a < 4; a++)
#pragma unroll
        for (int b = 0; b < 4; b++) acc[a][b] = 0.f;

    for (int kc = 0; kc < 128; kc += 32) {
        {
            int q = tid >> 2, kq = tid & 3;
            const float* src = g_u1 + (size_t)(qb + q)*128 + kc + kq*8;
            float4 v0 = ((const float4*)src)[0];
            float4 v1 = ((const float4*)src)[1];
            int k0 = kq*8;
            As[(k0+0)*68 + q] = v0.x; As[(k0+1)*68 + q] = v0.y;
            As[(k0+2)*68 + q] = v0.z; As[(k0+3)*68 + q] = v0.w;
            As[(k0+4)*68 + q] = v1.x; As[(k0+5)*68 + q] = v1.y;
            As[(k0+6)*68 + q] = v1.z; As[(k0+7)*68 + q] = v1.w;
        }
        {
            int k = tid >> 3, jb = (tid & 7) * 8;
            const float4* src = (const float4*)(cw2 + (size_t)(kc + k)*64 + jb);
            float4* dst = (float4*)(Bs + k*64 + jb);
            dst[0] = src[0]; dst[1] = src[1];
        }
        __syncthreads();
#pragma unroll
        for (int k = 0; k < 32; k++) {
            float4 av = *(const float4*)(As + k*68 + qg);
            float4 bv = *(const float4*)(Bs + k*64 + j0);
            acc[0][0] += av.x*bv.x; acc[0][1] += av.x*bv.y; acc[0][2] += av.x*bv.z; acc[0][3] += av.x*bv.w;
            acc[1][0] += av.y*bv.x; acc[1][1] += av.y*bv.y; acc[1][2] += av.y*bv.z; acc[1][3] += av.y*bv.w;
            acc[2][0] += av.z*bv.x; acc[2][1] += av.z*bv.y; acc[2][2] += av.z*bv.z; acc[2][3] += av.z*bv.w;
            acc[3][0] += av.w*bv.x; acc[3][1] += av.w*bv.y; acc[3][2] += av.w*bv.z; acc[3][3] += av.w*bv.w;
        }
        __syncthreads();
    }

#pragma unroll
    for (int qi = 0; qi < 4; qi++) {
        int gq = qb + qg + qi;
        int bb = gq / 3;
        int slot = gq - bb*3;
        float* dst = g_feat2 + (size_t)bb*193 + slot*64 + j0;
#pragma unroll
        for (int j = 0; j < 4; j++) {
            float h = acc[qi][j] + cb2[j0 + j];
            dst[j] = h > 0.f ? h : 0.f;
        }
    }
}

// ---------------------------------------------------------------------------
// K6: out[b] = relu(feat2 @ sw1 + sb1) @ sw2 + sb2
// Block = 32 b; sw1 (99KB) staged ONCE per block in dynamic smem.
// ---------------------------------------------------------------------------
__global__ void __launch_bounds__(256)
its_score_kernel(const float* __restrict__ sw1, const float* __restrict__ sb1,
                 const float* __restrict__ sw2, const float* __restrict__ sb2,
                 const float* __restrict__ d_norm, float* __restrict__ out) {
    extern __shared__ float smsc[];
    float* s_w1 = smsc;              // [193*128]
    float* srow = smsc + 24704;      // [8][200]
    int tid = threadIdx.x;
    int w = tid >> 5, lane = tid & 31;

    for (int i = tid; i < 6176; i += 256)
        ((float4*)s_w1)[i] = ((const float4*)sw1)[i];
    __syncthreads();

    float4 w2v = *(const float4*)(sw2 + lane*4);
    float sbias = sb2[0];
    float b1v0 = sb1[lane*4+0], b1v1 = sb1[lane*4+1];
    float b1v2 = sb1[lane*4+2], b1v3 = sb1[lane*4+3];

#pragma unroll
    for (int sub = 0; sub < 4; sub++) {
        int b = blockIdx.x * 32 + w * 4 + sub;
        for (int k = lane; k < 192; k += 32)
            srow[w*200 + k] = g_feat2[(size_t)b*193 + k];
        if (lane == 0) srow[w*200 + 192] = d_norm[b];
        __syncwarp();

        float a0 = 0.f, a1 = 0.f, a2 = 0.f, a3 = 0.f;
        for (int k = 0; k < 193; k++) {
            float f = srow[w*200 + k];
            float4 wv = *(const float4*)(s_w1 + k*128 + lane*4);
            a0 += f*wv.x; a1 += f*wv.y; a2 += f*wv.z; a3 += f*wv.w;
        }
        float v0 = fmaxf(a0 + b1v0, 0.f);
        float v1 = fmaxf(a1 + b1v1, 0.f);
        float v2 = fmaxf(a2 + b1v2, 0.f);
        float v3 = fmaxf(a3 + b1v3, 0.f);
        float p = v0*w2v.x + v1*w2v.y + v2*w2v.z + v3*w2v.w;
#pragma unroll
        for (int off = 16; off > 0; off >>= 1)
            p += __shfl_xor_sync(0xffffffffu, p, off);
        if (lane == 0) out[b] = p + sbias;
        __syncwarp();
    }
}

// ---------------------------------------------------------------------------
// kernel_launch
// ---------------------------------------------------------------------------
extern "C" void kernel_launch(void* const* d_in, const int* in_sizes, int n_in,
                              void* d_out, int out_size) {
    const float* x       = (const float*)d_in[0];
    const float* d_norm  = (const float*)d_in[1];
    const float* demb    = (const float*)d_in[2];
    const float* piw1    = (const float*)d_in[3];
    const float* pib1    = (const float*)d_in[4];
    const float* piw2    = (const float*)d_in[5];
    const float* pib2    = (const float*)d_in[6];
    const float* pow1    = (const float*)d_in[7];
    const float* pob1    = (const float*)d_in[8];
    const float* pow2    = (const float*)d_in[9];
    const float* pob2    = (const float*)d_in[10];
    const float* cw1     = (const float*)d_in[11];
    const float* cb1     = (const float*)d_in[12];
    const float* cw2     = (const float*)d_in[13];
    const float* cb2     = (const float*)d_in[14];
    const float* sw1     = (const float*)d_in[15];
    const float* sb1     = (const float*)d_in[16];
    const float* sw2     = (const float*)d_in[17];
    const float* sb2     = (const float*)d_in[18];
    const int* node_ids  = (const int*)d_in[19];
    const int* times     = (const int*)d_in[20];
    const int* in_u      = (const int*)d_in[21];
    const int* in_tau    = (const int*)d_in[22];
    const void* in_mask  = d_in[23];
    const int* out_u     = (const int*)d_in[24];
    const int* out_tau   = (const int*)d_in[25];
    const void* out_mask = d_in[26];
    float* out = (float*)d_out;

    cudaFuncSetAttribute(its_edge_kernel,
                         cudaFuncAttributeMaxDynamicSharedMemorySize, SMEM_EK);
    cudaFuncSetAttribute(its_score_kernel,
                         cudaFuncAttributeMaxDynamicSharedMemorySize, SMEM_SC);

    its_detect_kernel<<<1, 256>>>((const unsigned int*)in_mask);
    its_tables_kernel<<<2, 256>>>(demb, piw1, pib1, pow1, pob1);
    its_edge_kernel<<<2*EBLK, 256, SMEM_EK>>>(x,
        in_u, in_tau, in_mask, out_u, out_tau, out_mask, times, piw1, pow1);
    its_combine_a_kernel<<<QQ/QT, 256>>>(x, node_ids, times, piw2, pib2, pow2, pob2);
    its_gemm1_kernel<<<QQ/64, 256>>>(cw1, cb1);
    its_gemm2_kernel<<<QQ/64, 256>>>(cw2, cb2);
    its_score_kernel<<<BB/32, 256, SMEM_SC>>>(sw1, sb1, sw2, sb2, d_norm, out);
}

// round 15
// speedup vs baseline: 1.8626x; 1.0753x over previous
#include <cuda_runtime.h>
#include <cuda_bf16.h>
#include <cstdint>

// ---------------------------------------------------------------------------
// Problem constants
// ---------------------------------------------------------------------------
#define NN      20000
#define TT      64
#define FF      128
#define BB      8192
#define KK      32
#define QQ      (3*BB)            // 24576
#define WWIN    64
#define QK      (QQ*KK)           // 786432
#define TILE_E  64                // edges per tile (= 2 full queries)
#define TILES2  (QK/TILE_E)       // 12288 tiles per direction
#define NTILE   8                 // tiles per block (w1 staged once)
#define EBLK    (TILES2/NTILE)    // 1536 blocks per direction

// Edge-kernel dynamic smem: As[128][68] | Bs[128][68] | spart[16][64] f32 + srowS/sdeltaS[256] int
#define SMEM_EK ((128*68 + 128*68 + 16*64) * 4 + 512*4)   // 75776 B -> occupancy 3

// Score-kernel dynamic smem (floats): s_w1[193*128] | srow[8][200]
#define SMEM_SC ((193*128 + 8*200) * 4)                   // 105216 B

// ---------------------------------------------------------------------------
// Device scratch (static __device__ arrays — allocation APIs are forbidden)
// ---------------------------------------------------------------------------
__device__ int    g_flags[2];                 // [0]=not01, [1]=not0f
__device__ float  g_demb[2*65*64];            // per-dir (delta_emb@w1_delta + b1)
__device__ float  g_hsum[2*(size_t)QQ*64];    // per-(dir,query) sum of relu hidden
__device__ int    g_cnt[2*QQ];                // per-(dir,query) valid-edge count
__device__ float  g_feat[(size_t)QQ*256];     // [x_vt | m_in | m_out]
__device__ float  g_u1[(size_t)QQ*128];       // combine hidden 1
__device__ float  g_feat2[(size_t)BB*193];    // scorer features

// ---------------------------------------------------------------------------
// f32x2 helpers (sm_103a packed fp32 — 2x FFMA throughput)
// ---------------------------------------------------------------------------
__device__ __forceinline__ unsigned long long ffma2(unsigned long long a,
                                                    unsigned long long b,
                                                    unsigned long long c) {
    unsigned long long d;
    asm("fma.rn.f32x2 %0, %1, %2, %3;" : "=l"(d) : "l"(a), "l"(b), "l"(c));
    return d;
}
__device__ __forceinline__ unsigned long long dup2(float v) {
    unsigned long long r;
    asm("mov.b64 %0, {%1, %2};" : "=l"(r) : "f"(v), "f"(v));
    return r;
}
__device__ __forceinline__ float2 unpack2(unsigned long long v) {
    float2 r;
    asm("mov.b64 {%0, %1}, %2;" : "=f"(r.x), "=f"(r.y) : "l"(v));
    return r;
}
__device__ __forceinline__ int read_mask(const void* p, int idx, int mode) {
    if (mode == 1) return ((const int*)p)[idx] != 0;
    if (mode == 2) return ((const float*)p)[idx] != 0.0f;
    return ((const unsigned char*)p)[idx] != 0;
}

// ---------------------------------------------------------------------------
// K0a: reset detect flags (graph-replay safe)
// ---------------------------------------------------------------------------
__global__ void its_reset_kernel() {
    g_flags[0] = 0;
    g_flags[1] = 0;
}

// ---------------------------------------------------------------------------
// K0b: classify mask serialization, parallel (64 blocks, deterministic
// final flag values via atomicOr).
// ---------------------------------------------------------------------------
__global__ void its_detect_kernel(const unsigned int* __restrict__ m) {
    int l01 = 0, l0f = 0;
    for (int i = blockIdx.x * blockDim.x + threadIdx.x; i < QK/4;
         i += gridDim.x * blockDim.x) {
        unsigned v = m[i];
        if (v > 1u) l01 = 1;
        if (v != 0u && v != 0x3F800000u) l0f = 1;
    }
    l01 = __syncthreads_or(l01);
    l0f = __syncthreads_or(l0f);
    if (threadIdx.x == 0) {
        if (l01) atomicOr(&g_flags[0], 1);
        if (l0f) atomicOr(&g_flags[1], 1);
    }
}

// ---------------------------------------------------------------------------
// K1: delta tables: g_demb[dir][d][j] = delta_emb[d] @ w1[128:144, :] + b1[j]
// ---------------------------------------------------------------------------
__global__ void its_tables_kernel(const float* __restrict__ demb,
                                  const float* __restrict__ piw1, const float* __restrict__ pib1,
                                  const float* __restrict__ pow1, const float* __restrict__ pob1) {
    int dir = blockIdx.x;
    const float* w1 = dir ? pow1 : piw1;
    const float* b1 = dir ? pob1 : pib1;
    float* out = g_demb + dir * (65*64);
    for (int idx = threadIdx.x; idx < 65*64; idx += blockDim.x) {
        int d = idx >> 6, j = idx & 63;
        float acc = b1[j];
#pragma unroll
        for (int dd = 0; dd < 16; dd++)
            acc += demb[d*16 + dd] * w1[(128 + dd)*64 + j];
        out[idx] = acc;
    }
}

// ---------------------------------------------------------------------------
// K2: edge aggregation — WARP-AUTONOMOUS tiles.
// Block = 1 dir x NTILE tiles (16 queries); w1 staged once per block.
// Per tile, each warp independently: loads its query's 32 slots (4x
// redundant, L1-hot), ballot-compacts into per-warp smem scratch, gathers
// its own 8 compacted edges into its private As columns, runs the FFMA2
// GEMM, and computes masked partials — NO block syncs until the cross-warp
// reduce (2 syncs/tile instead of 4; gather latency hidden per-warp).
// ---------------------------------------------------------------------------
__global__ void __launch_bounds__(256, 3)
its_edge_kernel(const float* __restrict__ x,
                const int* __restrict__ in_u,  const int* __restrict__ in_tau,
                const void* __restrict__ in_mask,
                const int* __restrict__ out_u, const int* __restrict__ out_tau,
                const void* __restrict__ out_mask,
                const int* __restrict__ times,
                const float* __restrict__ piw1, const float* __restrict__ pow1) {
    extern __shared__ float sm[];
    float* As    = sm;               // [128 k][68]  (64 edge slots + pad)
    float* Bs    = As + 128*68;      // [128 k][68]  (64 j + pad)
    float* spart = Bs + 128*68;      // [16 groups][64]
    int* srowS   = (int*)(spart + 16*64);  // [8 warps][32] compacted rows
    int* sdeltaS = srowS + 256;            // [8 warps][32] compacted deltas

    int bid  = blockIdx.x;
    int dir  = (bid >= EBLK) ? 1 : 0;
    int bslot = bid - dir * EBLK;
    const int*  uu = dir ? out_u   : in_u;
    const int*  tt = dir ? out_tau : in_tau;
    const void* mm = dir ? out_mask : in_mask;
    const float* w1 = dir ? pow1 : piw1;
    const float* gdemb = g_demb + dir * 4160;
    int tid = threadIdx.x;
    int wid = tid >> 5, lane = tid & 31;
    int mode;
    {
        int f01 = g_flags[0], f0f = g_flags[1];
        mode = (!f01) ? 1 : ((!f0f) ? 2 : 0);
    }

    // Stage w1 rows 0..127 ONCE per block (8192 floats)
    for (int i = tid; i < 2048; i += 256) {
        float4 v = ((const float4*)w1)[i];
        int k = i >> 4, j = (i & 15) * 4;
        *(float4*)(Bs + k*68 + j) = v;
    }
    __syncthreads();   // Bs visible to all warps before first GEMM

    // Warp-invariant coordinates
    int wq   = wid >> 2;                    // warp's query within tile (0/1)
    int ebq  = (wid & 3) * 8;               // warp's edge base within query
    int r0   = wid*8 + ((lane >> 4) << 2);  // As column base for GEMM
    int o0   = (lane & 15) * 4;             // j base
    int te   = wid*2 + (lane >> 4);         // spart group

    for (int it = 0; it < NTILE; it++) {
        int tile = bslot * NTILE + it;
        int q = tile*2 + wq;

        // --- per-warp metadata + compaction (redundant across the 4 warps
        //     of a query; all reads L1-hot) ---
        {
            int s = tile*TILE_E + wq*32 + lane;
            int t = times[q];
            int u = uu[s], ta = tt[s];
            int d = dir ? (ta - t) : (t - ta);
            d = d < 0 ? 0 : (d > WWIN ? WWIN : d);
            int mk = read_mask(mm, s, mode);
            unsigned bal = __ballot_sync(0xffffffffu, mk);
            int cnt = __popc(bal);
            int pos = __popc(bal & ((1u << lane) - 1u));
            if (mk) {
                srowS[wid*32 + pos]   = u*TT + ta;
                sdeltaS[wid*32 + pos] = d;
            }
            __syncwarp();
            if (ebq == 0 && lane == 0) g_cnt[dir*QQ + q] = cnt;

            int active = ebq < cnt;
            if (active) {
                // --- warp-local gather of its 8 compacted edges ---
                int el = ebq + (lane >> 2);    // compacted pos in query
                int h  = lane & 3;
                int eg = wq*32 + el;           // global As column
                if (el < cnt) {
                    int row = srowS[wid*32 + el];
                    const float4* src = (const float4*)(x + (size_t)row*128) + h*8;
#pragma unroll
                    for (int i = 0; i < 8; i++) {
                        float4 v = src[i];
                        int k0 = h*32 + i*4;
                        As[(k0+0)*68 + eg] = v.x;
                        As[(k0+1)*68 + eg] = v.y;
                        As[(k0+2)*68 + eg] = v.z;
                        As[(k0+3)*68 + eg] = v.w;
                    }
                } else {
#pragma unroll
                    for (int i = 0; i < 8; i++) {
                        int k0 = h*32 + i*4;
                        As[(k0+0)*68 + eg] = 0.0f;
                        As[(k0+1)*68 + eg] = 0.0f;
                        As[(k0+2)*68 + eg] = 0.0f;
                        As[(k0+3)*68 + eg] = 0.0f;
                    }
                }
                __syncwarp();

                // --- FFMA2 GEMM over this warp's 8 edges x 64 j ---
                unsigned long long acc[2][4];
#pragma unroll
                for (int p = 0; p < 2; p++)
#pragma unroll
                    for (int j = 0; j < 4; j++) acc[p][j] = 0ull;

#pragma unroll 8
                for (int k = 0; k < 128; k++) {
                    ulonglong2 a = *(const ulonglong2*)(As + k*68 + r0);
                    float4 bv = *(const float4*)(Bs + k*68 + o0);
                    unsigned long long b0 = dup2(bv.x), b1 = dup2(bv.y);
                    unsigned long long b2 = dup2(bv.z), b3 = dup2(bv.w);
                    acc[0][0] = ffma2(a.x, b0, acc[0][0]);
                    acc[0][1] = ffma2(a.x, b1, acc[0][1]);
                    acc[0][2] = ffma2(a.x, b2, acc[0][2]);
                    acc[0][3] = ffma2(a.x, b3, acc[0][3]);
                    acc[1][0] = ffma2(a.y, b0, acc[1][0]);
                    acc[1][1] = ffma2(a.y, b1, acc[1][1]);
                    acc[1][2] = ffma2(a.y, b2, acc[1][2]);
                    acc[1][3] = ffma2(a.y, b3, acc[1][3]);
                }

                // --- epilogue: + demb[delta] (L1-hot), relu, masked partials ---
                float part[4] = {0.f, 0.f, 0.f, 0.f};
#pragma unroll
                for (int p = 0; p < 2; p++) {
                    int e0 = r0 + 2*p, e1 = e0 + 1;
                    int q0 = e0 & 31, q1 = e1 & 31;
                    int v0 = q0 < cnt, v1 = q1 < cnt;
                    float2 c0 = unpack2(acc[p][0]);
                    float2 c1 = unpack2(acc[p][1]);
                    float2 c2 = unpack2(acc[p][2]);
                    float2 c3 = unpack2(acc[p][3]);
                    if (v0) {
                        float4 dv = *(const float4*)(gdemb + sdeltaS[wid*32 + q0]*64 + o0);
                        part[0] += fmaxf(c0.x + dv.x, 0.f);
                        part[1] += fmaxf(c1.x + dv.y, 0.f);
                        part[2] += fmaxf(c2.x + dv.z, 0.f);
                        part[3] += fmaxf(c3.x + dv.w, 0.f);
                    }
                    if (v1) {
                        float4 dv = *(const float4*)(gdemb + sdeltaS[wid*32 + q1]*64 + o0);
                        part[0] += fmaxf(c0.y + dv.x, 0.f);
                        part[1] += fmaxf(c1.y + dv.y, 0.f);
                        part[2] += fmaxf(c2.y + dv.z, 0.f);
                        part[3] += fmaxf(c3.y + dv.w, 0.f);
                    }
                }
                spart[te*64 + o0 + 0] = part[0];
                spart[te*64 + o0 + 1] = part[1];
                spart[te*64 + o0 + 2] = part[2];
                spart[te*64 + o0 + 3] = part[3];
            } else {
                spart[te*64 + o0 + 0] = 0.f;
                spart[te*64 + o0 + 1] = 0.f;
                spart[te*64 + o0 + 2] = 0.f;
                spart[te*64 + o0 + 3] = 0.f;
            }
        }
        __syncthreads();

        // Deterministic reduce: 8 groups per query
        if (tid < 128) {
            int rq = tid >> 6, j = tid & 63;
            float s = 0.f;
#pragma unroll
            for (int g = 0; g < 8; g++) s += spart[(rq*8 + g)*64 + j];
            g_hsum[(size_t)dir*QQ*64 + (size_t)(tile*2 + rq)*64 + j] = s;
        }
        __syncthreads();   // spart / scratch safe for next tile
    }
}

// ---------------------------------------------------------------------------
// K3: per-query m_in/m_out (hsum @ w2 / cnt + b2) + x_vt gather -> g_feat[Q,256]
// ---------------------------------------------------------------------------
#define QT 24
__global__ void __launch_bounds__(256)
its_combine_a_kernel(const float* __restrict__ x,
                     const int* __restrict__ node_ids, const int* __restrict__ times,
                     const float* __restrict__ piw2, const float* __restrict__ pib2,
                     const float* __restrict__ pow2, const float* __restrict__ pob2) {
    __shared__ float s_w2[2*64*64];
    __shared__ float s_hs[2*QT*64];
    __shared__ float s_b2[2*64];
    __shared__ int   s_cnt[2*QT];

    int qb = blockIdx.x * QT;
    int tid = threadIdx.x;

    for (int i = tid; i < 4096; i += 256) {
        s_w2[i]        = piw2[i];
        s_w2[4096 + i] = pow2[i];
    }
    if (tid < 64) { s_b2[tid] = pib2[tid]; s_b2[64 + tid] = pob2[tid]; }
    for (int i = tid; i < QT*64; i += 256) {
        int qi = i >> 6, j = i & 63;
        s_hs[i]         = g_hsum[(size_t)(qb + qi)*64 + j];
        s_hs[QT*64 + i] = g_hsum[(size_t)QQ*64 + (size_t)(qb + qi)*64 + j];
    }
    if (tid < 2*QT) {
        int dir = tid >= QT, qi = tid - dir*QT;
        s_cnt[tid] = g_cnt[dir*QQ + qb + qi];
    }
    __syncthreads();

    for (int task = tid; task < 2*QT*8; task += 256) {
        int r = task >> 3, c = task & 7;
        int dir = r >= QT, qi = r - dir*QT;
        const float* hs = s_hs + dir*QT*64 + qi*64;
        const float* w2 = s_w2 + dir*4096;
        float acc[8] = {0,0,0,0,0,0,0,0};
#pragma unroll 8
        for (int k = 0; k < 64; k++) {
            float h = hs[k];
            const float* wr = w2 + k*64 + c*8;
            float4 w0 = *(const float4*)wr;
            float4 w1 = *(const float4*)(wr + 4);
            acc[0] += h*w0.x; acc[1] += h*w0.y; acc[2] += h*w0.z; acc[3] += h*w0.w;
            acc[4] += h*w1.x; acc[5] += h*w1.y; acc[6] += h*w1.z; acc[7] += h*w1.w;
        }
        int cnt = s_cnt[dir*QT + qi];
        float inv = 1.0f / (float)(cnt > 1 ? cnt : 1);
        float bsc = cnt > 0 ? 1.0f : 0.0f;
        float* dst = g_feat + (size_t)(qb + qi)*256 + 128 + dir*64 + c*8;
#pragma unroll
        for (int j = 0; j < 8; j++)
            dst[j] = acc[j]*inv + bsc * s_b2[dir*64 + c*8 + j];
    }

    for (int task = tid; task < QT*16; task += 256) {
        int qi = task >> 4, part = task & 15;
        int q = qb + qi;
        const float* src = x + (size_t)node_ids[q]*8192 + (size_t)times[q]*128 + part*8;
        float* dst = g_feat + (size_t)q*256 + part*8;
        float4 a = ((const float4*)src)[0];
        float4 b = ((const float4*)src)[1];
        ((float4*)dst)[0] = a;
        ((float4*)dst)[1] = b;
    }
}

// ---------------------------------------------------------------------------
// K4: u1 = relu(feat @ cw1 + cb1)   [Q,256]@[256,128]
// ---------------------------------------------------------------------------
__global__ void __launch_bounds__(256)
its_gemm1_kernel(const float* __restrict__ cw1, const float* __restrict__ cb1) {
    __shared__ float As[32*68];
    __shared__ float Bs[32*128];
    int qb = blockIdx.x * 64;
    int tid = threadIdx.x;
    int qg = (tid >> 4) * 4;
    int j0 = (tid & 15) * 8;

    unsigned long long acc[4][4];
#pragma unroll
    for (int a = 0; a < 4; a++)
#pragma unroll
        for (int b = 0; b < 4; b++) acc[a][b] = 0ull;

    for (int kc = 0; kc < 256; kc += 32) {
        {
            int q = tid >> 2, kq = tid & 3;
            const float* src = g_feat + (size_t)(qb + q)*256 + kc + kq*8;
            float4 v0 = ((const float4*)src)[0];
            float4 v1 = ((const float4*)src)[1];
            int k0 = kq*8;
            As[(k0+0)*68 + q] = v0.x; As[(k0+1)*68 + q] = v0.y;
            As[(k0+2)*68 + q] = v0.z; As[(k0+3)*68 + q] = v0.w;
            As[(k0+4)*68 + q] = v1.x; As[(k0+5)*68 + q] = v1.y;
            As[(k0+6)*68 + q] = v1.z; As[(k0+7)*68 + q] = v1.w;
        }
        {
            int k = tid >> 3, jb = (tid & 7) * 16;
            const float4* src = (const float4*)(cw1 + (size_t)(kc + k)*128 + jb);
            float4* dst = (float4*)(Bs + k*128 + jb);
            dst[0] = src[0]; dst[1] = src[1]; dst[2] = src[2]; dst[3] = src[3];
        }
        __syncthreads();
#pragma unroll
        for (int k = 0; k < 32; k++) {
            float4 av = *(const float4*)(As + k*68 + qg);
            ulonglong2 bA = *(const ulonglong2*)(Bs + k*128 + j0);
            ulonglong2 bB = *(const ulonglong2*)(Bs + k*128 + j0 + 4);
            unsigned long long a0 = dup2(av.x), a1 = dup2(av.y);
            unsigned long long a2 = dup2(av.z), a3 = dup2(av.w);
            acc[0][0] = ffma2(a0, bA.x, acc[0][0]); acc[0][1] = ffma2(a0, bA.y, acc[0][1]);
            acc[0][2] = ffma2(a0, bB.x, acc[0][2]); acc[0][3] = ffma2(a0, bB.y, acc[0][3]);
            acc[1][0] = ffma2(a1, bA.x, acc[1][0]); acc[1][1] = ffma2(a1, bA.y, acc[1][1]);
            acc[1][2] = ffma2(a1, bB.x, acc[1][2]); acc[1][3] = ffma2(a1, bB.y, acc[1][3]);
            acc[2][0] = ffma2(a2, bA.x, acc[2][0]); acc[2][1] = ffma2(a2, bA.y, acc[2][1]);
            acc[2][2] = ffma2(a2, bB.x, acc[2][2]); acc[2][3] = ffma2(a2, bB.y, acc[2][3]);
            acc[3][0] = ffma2(a3, bA.x, acc[3][0]); acc[3][1] = ffma2(a3, bA.y, acc[3][1]);
            acc[3][2] = ffma2(a3, bB.x, acc[3][2]); acc[3][3] = ffma2(a3, bB.y, acc[3][3]);
        }
        __syncthreads();
    }

#pragma unroll
    for (int jp = 0; jp < 4; jp++) {
        int j = j0 + jp*2;
        float b0 = cb1[j], b1 = cb1[j+1];
#pragma unroll
        for (int qi = 0; qi < 4; qi++) {
            float2 v = unpack2(acc[qi][jp]);
            float r0 = v.x + b0; r0 = r0 > 0.f ? r0 : 0.f;
            float r1 = v.y + b1; r1 = r1 > 0.f ? r1 : 0.f;
            float* dst = g_u1 + (size_t)(qb + qg + qi)*128 + j;
            dst[0] = r0; dst[1] = r1;
        }
    }
}

// ---------------------------------------------------------------------------
// K5: h = relu(u1 @ cw2 + cb2)  [Q,128]@[128,64] -> scatter into g_feat2
// ---------------------------------------------------------------------------
__global__ void __launch_bounds__(256)
its_gemm2_kernel(const float* __restrict__ cw2, const float* __restrict__ cb2) {
    __shared__ float As[32*68];
    __shared__ float Bs[32*64];
    int qb = blockIdx.x * 64;
    int tid = threadIdx.x;
    int qg = (tid >> 4) * 4;
    int j0 = (tid & 15) * 4;

    float acc[4][4];
#pragma unroll
    for (int a = 0; a < 4; a++)
#pragma unroll
        for (int b = 0; b < 4; b++) acc[a][b] = 0.f;

    for (int kc = 0; kc < 128; kc += 32) {
        {
            int q = tid >> 2, kq = tid & 3;
            const float* src = g_u1 + (size_t)(qb + q)*128 + kc + kq*8;
            float4 v0 = ((const float4*)src)[0];
            float4 v1 = ((const float4*)src)[1];
            int k0 = kq*8;
            As[(k0+0)*68 + q] = v0.x; As[(k0+1)*68 + q] = v0.y;
            As[(k0+2)*68 + q] = v0.z; As[(k0+3)*68 + q] = v0.w;
            As[(k0+4)*68 + q] = v1.x; As[(k0+5)*68 + q] = v1.y;
            As[(k0+6)*68 + q] = v1.z; As[(k0+7)*68 + q] = v1.w;
        }
        {
            int k = tid >> 3, jb = (tid & 7) * 8;
            const float4* src = (const float4*)(cw2 + (size_t)(kc + k)*64 + jb);
            float4* dst = (float4*)(Bs + k*64 + jb);
            dst[0] = src[0]; dst[1] = src[1];
        }
        __syncthreads();
#pragma unroll
        for (int k = 0; k < 32; k++) {
            float4 av = *(const float4*)(As + k*68 + qg);
            float4 bv = *(const float4*)(Bs + k*64 + j0);
            acc[0][0] += av.x*bv.x; acc[0][1] += av.x*bv.y; acc[0][2] += av.x*bv.z; acc[0][3] += av.x*bv.w;
            acc[1][0] += av.y*bv.x; acc[1][1] += av.y*bv.y; acc[1][2] += av.y*bv.z; acc[1][3] += av.y*bv.w;
            acc[2][0] += av.z*bv.x; acc[2][1] += av.z*bv.y; acc[2][2] += av.z*bv.z; acc[2][3] += av.z*bv.w;
            acc[3][0] += av.w*bv.x; acc[3][1] += av.w*bv.y; acc[3][2] += av.w*bv.z; acc[3][3] += av.w*bv.w;
        }
        __syncthreads();
    }

#pragma unroll
    for (int qi = 0; qi < 4; qi++) {
        int gq = qb + qg + qi;
        int bb = gq / 3;
        int slot = gq - bb*3;
        float* dst = g_feat2 + (size_t)bb*193 + slot*64 + j0;
#pragma unroll
        for (int j = 0; j < 4; j++) {
            float h = acc[qi][j] + cb2[j0 + j];
            dst[j] = h > 0.f ? h : 0.f;
        }
    }
}

// ---------------------------------------------------------------------------
// K6: out[b] = relu(feat2 @ sw1 + sb1) @ sw2 + sb2
// Block = 32 b; sw1 (99KB) staged ONCE per block in dynamic smem.
// ---------------------------------------------------------------------------
__global__ void __launch_bounds__(256)
its_score_kernel(const float* __restrict__ sw1, const float* __restrict__ sb1,
                 const float* __restrict__ sw2, const float* __restrict__ sb2,
                 const float* __restrict__ d_norm, float* __restrict__ out) {
    extern __shared__ float smsc[];
    float* s_w1 = smsc;              // [193*128]
    float* srow = smsc + 24704;      // [8][200]
    int tid = threadIdx.x;
    int w = tid >> 5, lane = tid & 31;

    for (int i = tid; i < 6176; i += 256)
        ((float4*)s_w1)[i] = ((const float4*)sw1)[i];
    __syncthreads();

    float4 w2v = *(const float4*)(sw2 + lane*4);
    float sbias = sb2[0];
    float b1v0 = sb1[lane*4+0], b1v1 = sb1[lane*4+1];
    float b1v2 = sb1[lane*4+2], b1v3 = sb1[lane*4+3];

#pragma unroll
    for (int sub = 0; sub < 4; sub++) {
        int b = blockIdx.x * 32 + w * 4 + sub;
        for (int k = lane; k < 192; k += 32)
            srow[w*200 + k] = g_feat2[(size_t)b*193 + k];
        if (lane == 0) srow[w*200 + 192] = d_norm[b];
        __syncwarp();

        float a0 = 0.f, a1 = 0.f, a2 = 0.f, a3 = 0.f;
        for (int k = 0; k < 193; k++) {
            float f = srow[w*200 + k];
            float4 wv = *(const float4*)(s_w1 + k*128 + lane*4);
            a0 += f*wv.x; a1 += f*wv.y; a2 += f*wv.z; a3 += f*wv.w;
        }
        float v0 = fmaxf(a0 + b1v0, 0.f);
        float v1 = fmaxf(a1 + b1v1, 0.f);
        float v2 = fmaxf(a2 + b1v2, 0.f);
        float v3 = fmaxf(a3 + b1v3, 0.f);
        float p = v0*w2v.x + v1*w2v.y + v2*w2v.z + v3*w2v.w;
#pragma unroll
        for (int off = 16; off > 0; off >>= 1)
            p += __shfl_xor_sync(0xffffffffu, p, off);
        if (lane == 0) out[b] = p + sbias;
        __syncwarp();
    }
}

// ---------------------------------------------------------------------------
// kernel_launch
// ---------------------------------------------------------------------------
extern "C" void kernel_launch(void* const* d_in, const int* in_sizes, int n_in,
                              void* d_out, int out_size) {
    const float* x       = (const float*)d_in[0];
    const float* d_norm  = (const float*)d_in[1];
    const float* demb    = (const float*)d_in[2];
    const float* piw1    = (const float*)d_in[3];
    const float* pib1    = (const float*)d_in[4];
    const float* piw2    = (const float*)d_in[5];
    const float* pib2    = (const float*)d_in[6];
    const float* pow1    = (const float*)d_in[7];
    const float* pob1    = (const float*)d_in[8];
    const float* pow2    = (const float*)d_in[9];
    const float* pob2    = (const float*)d_in[10];
    const float* cw1     = (const float*)d_in[11];
    const float* cb1     = (const float*)d_in[12];
    const float* cw2     = (const float*)d_in[13];
    const float* cb2     = (const float*)d_in[14];
    const float* sw1     = (const float*)d_in[15];
    const float* sb1     = (const float*)d_in[16];
    const float* sw2     = (const float*)d_in[17];
    const float* sb2     = (const float*)d_in[18];
    const int* node_ids  = (const int*)d_in[19];
    const int* times     = (const int*)d_in[20];
    const int* in_u      = (const int*)d_in[21];
    const int* in_tau    = (const int*)d_in[22];
    const void* in_mask  = d_in[23];
    const int* out_u     = (const int*)d_in[24];
    const int* out_tau   = (const int*)d_in[25];
    const void* out_mask = d_in[26];
    float* out = (float*)d_out;

    cudaFuncSetAttribute(its_edge_kernel,
                         cudaFuncAttributeMaxDynamicSharedMemorySize, SMEM_EK);
    cudaFuncSetAttribute(its_score_kernel,
                         cudaFuncAttributeMaxDynamicSharedMemorySize, SMEM_SC);

    its_reset_kernel<<<1, 1>>>();
    its_detect_kernel<<<64, 256>>>((const unsigned int*)in_mask);
    its_tables_kernel<<<2, 256>>>(demb, piw1, pib1, pow1, pob1);
    its_edge_kernel<<<2*EBLK, 256, SMEM_EK>>>(x,
        in_u, in_tau, in_mask, out_u, out_tau, out_mask, times, piw1, pow1);
    its_combine_a_kernel<<<QQ/QT, 256>>>(x, node_ids, times, piw2, pib2, pow2, pob2);
    its_gemm1_kernel<<<QQ/64, 256>>>(cw1, cb1);
    its_gemm2_kernel<<<QQ/64, 256>>>(cw2, cb2);
    its_score_kernel<<<BB/32, 256, SMEM_SC>>>(sw1, sb1, sw2, sb2, d_norm, out);
}